// round 1
// baseline (speedup 1.0000x reference)
#include <cuda_runtime.h>
#include <math.h>

#define BD    2
#define NSEQ  2048
#define CDIM  1024
#define RANK  64
#define HEADS 16
#define DH    64
#define MTOT  (BD*NSEQ)   // 4096

// Scratch (device globals: no allocation allowed in kernel_launch)
__device__ float g_h   [MTOT*RANK];            // gelu(x @ w_qkv_a)          1 MB
__device__ float g_q   [BD*HEADS*NSEQ*DH];     // scaled Q  [bh][n][d]      16 MB
__device__ float g_k   [BD*HEADS*NSEQ*DH];     // K                         16 MB
__device__ float g_v   [BD*HEADS*NSEQ*DH];     // V                         16 MB
__device__ float g_attn[MTOT*CDIM];            // attention out [B,N,C]     16 MB
__device__ float g_h2  [MTOT*RANK];            // gelu(attn @ w_proj_a + b)  1 MB

__device__ __forceinline__ float gelu_exact(float v) {
    return 0.5f * v * (1.0f + erff(v * 0.70710678118654752440f));
}

// ---------------------------------------------------------------------------
// out[M,64] = gelu(X[M,K] @ W[K,64] (+ bias))     (used for both LoRA "A" mats)
// Block: 32 rows x 64 cols, BK=32, 256 threads, 2x4 micro-tile.
// ---------------------------------------------------------------------------
__global__ __launch_bounds__(256) void lowrank_in_kernel(
    const float* __restrict__ X, const float* __restrict__ W,
    const float* __restrict__ bias, float* __restrict__ out, int K)
{
    __shared__ float Xs[32][33];
    __shared__ __align__(16) float Ws[32][68];
    const int tid = threadIdx.x;
    const int tx = tid & 15, ty = tid >> 4;
    const int m0 = blockIdx.x * 32;
    float acc[2][4] = {};
    for (int k0 = 0; k0 < K; k0 += 32) {
        for (int i = tid; i < 32*32; i += 256) {
            int r = i >> 5, k = i & 31;
            Xs[r][k] = X[(m0 + r) * K + k0 + k];
        }
        for (int i = tid; i < 32*64; i += 256) {
            int k = i >> 6, j = i & 63;
            Ws[k][j] = W[(k0 + k) * 64 + j];
        }
        __syncthreads();
        #pragma unroll
        for (int kk = 0; kk < 32; kk++) {
            float a0 = Xs[ty*2+0][kk];
            float a1 = Xs[ty*2+1][kk];
            float4 b = *(const float4*)&Ws[kk][tx*4];
            acc[0][0] += a0*b.x; acc[0][1] += a0*b.y; acc[0][2] += a0*b.z; acc[0][3] += a0*b.w;
            acc[1][0] += a1*b.x; acc[1][1] += a1*b.y; acc[1][2] += a1*b.z; acc[1][3] += a1*b.w;
        }
        __syncthreads();
    }
    #pragma unroll
    for (int i = 0; i < 2; i++)
        #pragma unroll
        for (int j = 0; j < 4; j++) {
            float v = acc[i][j];
            if (bias) v += bias[tx*4 + j];
            out[(m0 + ty*2 + i) * 64 + tx*4 + j] = gelu_exact(v);
        }
}

// ---------------------------------------------------------------------------
// qkv = g_h[4096,64] @ w_qkv_b[64,3072], scattered into g_q (x0.125), g_k, g_v
// with layout [b*H+h][n][d].   Block: 32 rows x 128 cols, 256 threads.
// ---------------------------------------------------------------------------
__global__ __launch_bounds__(256) void expand_qkv_kernel(const float* __restrict__ Wb)
{
    __shared__ __align__(16) float Hs[32][68];
    __shared__ __align__(16) float Ws[64][132];
    const int tid = threadIdx.x;
    const int tx = tid & 15, ty = tid >> 4;
    const int n0 = blockIdx.x * 128;
    const int m0 = blockIdx.y * 32;
    for (int i = tid; i < 32*64; i += 256) {
        int r = i >> 6, k = i & 63;
        Hs[r][k] = g_h[(m0 + r) * 64 + k];
    }
    for (int i = tid; i < 64*128; i += 256) {
        int k = i >> 7, c = i & 127;
        Ws[k][c] = Wb[k * (3*CDIM) + n0 + c];
    }
    __syncthreads();
    float acc[2][8] = {};
    #pragma unroll
    for (int kk = 0; kk < 64; kk++) {
        float a0 = Hs[ty*2+0][kk];
        float a1 = Hs[ty*2+1][kk];
        float4 b0 = *(const float4*)&Ws[kk][tx*8];
        float4 b1 = *(const float4*)&Ws[kk][tx*8+4];
        float bj[8] = {b0.x, b0.y, b0.z, b0.w, b1.x, b1.y, b1.z, b1.w};
        #pragma unroll
        for (int j = 0; j < 8; j++) { acc[0][j] += a0*bj[j]; acc[1][j] += a1*bj[j]; }
    }
    #pragma unroll
    for (int i = 0; i < 2; i++) {
        int m    = m0 + ty*2 + i;
        int bb   = m >> 11;         // / NSEQ
        int nseq = m & 2047;
        #pragma unroll
        for (int j = 0; j < 8; j++) {
            int gn   = n0 + tx*8 + j;
            int comp = gn >> 10;    // 0=q 1=k 2=v
            int c    = gn & 1023;
            int head = c >> 6;
            int d    = c & 63;
            int off  = ((bb*HEADS + head)*NSEQ + nseq)*DH + d;
            float v  = acc[i][j];
            if (comp == 0)      g_q[off] = v * 0.125f;   // Dh^-0.5
            else if (comp == 1) g_k[off] = v;
            else                g_v[off] = v;
        }
    }
}

// ---------------------------------------------------------------------------
// Flash attention, fp32. Grid (N/64, B*H). Block 128 threads.
// Br=Bc=64, online softmax, P staged via SMEM for the PV GEMM.
// Thread (tx=lane&7, ty=tid>>3): S rows ry=4*ty, S cols c=tx+8j (conflict-free
// K reads at LD=68); O cols d = {tx*4..+3} U {32+tx*4..+3} (conflict-free V reads).
// Writes result directly in [B,N,C] layout into g_attn.
// ---------------------------------------------------------------------------
#define FLD 68
#define FLASH_SMEM (4*64*FLD*4)

__global__ __launch_bounds__(128) void flash_kernel()
{
    extern __shared__ __align__(16) float sm[];
    float* Qs = sm;
    float* Ks = sm + 64*FLD;
    float* Vs = sm + 2*64*FLD;
    float* Ps = sm + 3*64*FLD;
    const int tid = threadIdx.x;
    const int tx = tid & 7, ty = tid >> 3;
    const int ry = ty * 4;
    const int bh = blockIdx.y;
    const int q0 = blockIdx.x * 64;
    const float* Qg = g_q + ((size_t)bh * NSEQ + q0) * DH;
    const float* Kg = g_k + (size_t)bh * NSEQ * DH;
    const float* Vg = g_v + (size_t)bh * NSEQ * DH;

    for (int i = tid; i < 64*16; i += 128) {
        int r = i >> 4, c4 = (i & 15) * 4;
        *(float4*)&Qs[r*FLD + c4] = *(const float4*)&Qg[r*DH + c4];
    }

    float o[4][8];
    float mrow[4], lrow[4];
    #pragma unroll
    for (int i = 0; i < 4; i++) {
        mrow[i] = -1e30f; lrow[i] = 0.f;
        #pragma unroll
        for (int j = 0; j < 8; j++) o[i][j] = 0.f;
    }

    for (int t = 0; t < NSEQ/64; t++) {
        __syncthreads();   // protect Ks/Vs/Ps from previous iteration's readers
        const float* Kt = Kg + t*64*DH;
        const float* Vt = Vg + t*64*DH;
        for (int i = tid; i < 64*16; i += 128) {
            int r = i >> 4, c4 = (i & 15) * 4;
            *(float4*)&Ks[r*FLD + c4] = *(const float4*)&Kt[r*DH + c4];
            *(float4*)&Vs[r*FLD + c4] = *(const float4*)&Vt[r*DH + c4];
        }
        __syncthreads();

        // S = Q K^T  (rows ry..ry+3, cols tx+8j)
        float s[4][8];
        #pragma unroll
        for (int i = 0; i < 4; i++)
            #pragma unroll
            for (int j = 0; j < 8; j++) s[i][j] = 0.f;
        #pragma unroll
        for (int d = 0; d < 64; d += 4) {
            float4 k4[8];
            #pragma unroll
            for (int j = 0; j < 8; j++)
                k4[j] = *(const float4*)&Ks[(tx + 8*j)*FLD + d];
            #pragma unroll
            for (int i = 0; i < 4; i++) {
                float4 q = *(const float4*)&Qs[(ry+i)*FLD + d];
                #pragma unroll
                for (int j = 0; j < 8; j++)
                    s[i][j] += q.x*k4[j].x + q.y*k4[j].y + q.z*k4[j].z + q.w*k4[j].w;
            }
        }

        // online softmax (row state replicated across the 8 tx lanes)
        #pragma unroll
        for (int i = 0; i < 4; i++) {
            float mx = s[i][0];
            #pragma unroll
            for (int j = 1; j < 8; j++) mx = fmaxf(mx, s[i][j]);
            #pragma unroll
            for (int off = 4; off > 0; off >>= 1)
                mx = fmaxf(mx, __shfl_xor_sync(0xffffffffu, mx, off));
            float mn    = fmaxf(mrow[i], mx);
            float alpha = __expf(mrow[i] - mn);
            mrow[i] = mn;
            float rs = 0.f;
            #pragma unroll
            for (int j = 0; j < 8; j++) {
                float p = __expf(s[i][j] - mn);
                rs += p;
                Ps[(ry+i)*FLD + tx + 8*j] = p;
            }
            #pragma unroll
            for (int off = 4; off > 0; off >>= 1)
                rs += __shfl_xor_sync(0xffffffffu, rs, off);
            lrow[i] = lrow[i]*alpha + rs;
            #pragma unroll
            for (int j = 0; j < 8; j++) o[i][j] *= alpha;
        }
        __syncthreads();

        // O += P @ V   (O cols: d = tx*4..+3 and 32+tx*4..+3)
        #pragma unroll 8
        for (int c = 0; c < 64; c++) {
            float4 v0 = *(const float4*)&Vs[c*FLD + tx*4];
            float4 v1 = *(const float4*)&Vs[c*FLD + 32 + tx*4];
            #pragma unroll
            for (int i = 0; i < 4; i++) {
                float p = Ps[(ry+i)*FLD + c];
                o[i][0] += p*v0.x; o[i][1] += p*v0.y; o[i][2] += p*v0.z; o[i][3] += p*v0.w;
                o[i][4] += p*v1.x; o[i][5] += p*v1.y; o[i][6] += p*v1.z; o[i][7] += p*v1.w;
            }
        }
    }

    const int b = bh >> 4, h = bh & 15;
    #pragma unroll
    for (int i = 0; i < 4; i++) {
        float inv = 1.0f / lrow[i];
        size_t base = ((size_t)(b*NSEQ + q0 + ry + i))*CDIM + h*DH;
        float4 a0 = make_float4(o[i][0]*inv, o[i][1]*inv, o[i][2]*inv, o[i][3]*inv);
        float4 a1 = make_float4(o[i][4]*inv, o[i][5]*inv, o[i][6]*inv, o[i][7]*inv);
        *(float4*)&g_attn[base + tx*4]      = a0;
        *(float4*)&g_attn[base + 32 + tx*4] = a1;
    }
}

// ---------------------------------------------------------------------------
// y[M,1024] = g_h2[M,64] @ w_proj_b[64,1024] + b_proj_b
// ---------------------------------------------------------------------------
__global__ __launch_bounds__(256) void lowrank_out_kernel(
    const float* __restrict__ Wb, const float* __restrict__ bias,
    float* __restrict__ out)
{
    __shared__ __align__(16) float Hs[32][68];
    __shared__ __align__(16) float Ws[64][132];
    const int tid = threadIdx.x;
    const int tx = tid & 15, ty = tid >> 4;
    const int n0 = blockIdx.x * 128;
    const int m0 = blockIdx.y * 32;
    for (int i = tid; i < 32*64; i += 256) {
        int r = i >> 6, k = i & 63;
        Hs[r][k] = g_h2[(m0 + r) * 64 + k];
    }
    for (int i = tid; i < 64*128; i += 256) {
        int k = i >> 7, c = i & 127;
        Ws[k][c] = Wb[k * CDIM + n0 + c];
    }
    __syncthreads();
    float acc[2][8] = {};
    #pragma unroll
    for (int kk = 0; kk < 64; kk++) {
        float a0 = Hs[ty*2+0][kk];
        float a1 = Hs[ty*2+1][kk];
        float4 b0 = *(const float4*)&Ws[kk][tx*8];
        float4 b1 = *(const float4*)&Ws[kk][tx*8+4];
        float bj[8] = {b0.x, b0.y, b0.z, b0.w, b1.x, b1.y, b1.z, b1.w};
        #pragma unroll
        for (int j = 0; j < 8; j++) { acc[0][j] += a0*bj[j]; acc[1][j] += a1*bj[j]; }
    }
    float4 bv0 = *(const float4*)&bias[n0 + tx*8];
    float4 bv1 = *(const float4*)&bias[n0 + tx*8 + 4];
    #pragma unroll
    for (int i = 0; i < 2; i++) {
        size_t base = (size_t)(m0 + ty*2 + i)*CDIM + n0 + tx*8;
        float4 r0 = make_float4(acc[i][0]+bv0.x, acc[i][1]+bv0.y, acc[i][2]+bv0.z, acc[i][3]+bv0.w);
        float4 r1 = make_float4(acc[i][4]+bv1.x, acc[i][5]+bv1.y, acc[i][6]+bv1.z, acc[i][7]+bv1.w);
        *(float4*)&out[base]     = r0;
        *(float4*)&out[base + 4] = r1;
    }
}

// ---------------------------------------------------------------------------
extern "C" void kernel_launch(void* const* d_in, const int* in_sizes, int n_in,
                              void* d_out, int out_size)
{
    const float* x        = (const float*)d_in[0];
    const float* w_qkv_a  = (const float*)d_in[1];
    const float* w_qkv_b  = (const float*)d_in[2];
    const float* w_proj_a = (const float*)d_in[3];
    const float* b_proj_a = (const float*)d_in[4];
    const float* w_proj_b = (const float*)d_in[5];
    const float* b_proj_b = (const float*)d_in[6];
    float* out = (float*)d_out;

    float *ph = nullptr, *ph2 = nullptr, *pattn = nullptr;
    cudaGetSymbolAddress((void**)&ph,    g_h);
    cudaGetSymbolAddress((void**)&ph2,   g_h2);
    cudaGetSymbolAddress((void**)&pattn, g_attn);

    // 1. h = gelu(x @ w_qkv_a)                    [4096,64]
    lowrank_in_kernel<<<MTOT/32, 256>>>(x, w_qkv_a, nullptr, ph, CDIM);
    // 2. qkv = h @ w_qkv_b  -> scatter q(*scale)/k/v
    expand_qkv_kernel<<<dim3(3*CDIM/128, MTOT/32), 256>>>(w_qkv_b);
    // 3. flash attention -> g_attn [B,N,C]
    cudaFuncSetAttribute(flash_kernel, cudaFuncAttributeMaxDynamicSharedMemorySize, FLASH_SMEM);
    flash_kernel<<<dim3(NSEQ/64, BD*HEADS), 128, FLASH_SMEM>>>();
    // 4. h2 = gelu(attn @ w_proj_a + b_proj_a)    [4096,64]
    lowrank_in_kernel<<<MTOT/32, 256>>>(pattn, w_proj_a, b_proj_a, ph2, CDIM);
    // 5. y = h2 @ w_proj_b + b_proj_b             [4096,1024]
    lowrank_out_kernel<<<dim3(CDIM/128, MTOT/32), 256>>>(w_proj_b, b_proj_b, out);
}

// round 3
// speedup vs baseline: 2.4840x; 2.4840x over previous
#include <cuda_runtime.h>
#include <math.h>

#define BD    2
#define NSEQ  2048
#define CDIM  1024
#define RANK  64
#define HEADS 16
#define DH    64
#define MTOT  (BD*NSEQ)   // 4096

// Scratch (device globals: no allocation allowed in kernel_launch)
__device__ float g_h   [MTOT*RANK];            // gelu(x @ w_qkv_a)
__device__ float g_q   [BD*HEADS*NSEQ*DH];     // scaled Q, tf32-rounded [bh][n][d]
__device__ float g_k   [BD*HEADS*NSEQ*DH];     // K, tf32-rounded       [bh][n][d]
__device__ float g_vT  [BD*HEADS*DH*NSEQ];     // V^T, tf32-rounded     [bh][d][n]
__device__ float g_attn[MTOT*CDIM];            // attention out [B,N,C]
__device__ float g_h2  [MTOT*RANK];            // gelu(attn @ w_proj_a + b)

__device__ __forceinline__ float gelu_exact(float v) {
    return 0.5f * v * (1.0f + erff(v * 0.70710678118654752440f));
}
__device__ __forceinline__ float tf32r(float x) {
    unsigned u;
    asm("cvt.rna.tf32.f32 %0, %1;" : "=r"(u) : "f"(x));
    return __uint_as_float(u);
}
__device__ __forceinline__ void ldsm4(unsigned &r0, unsigned &r1, unsigned &r2, unsigned &r3, unsigned a) {
    asm volatile("ldmatrix.sync.aligned.m8n8.x4.shared.b16 {%0,%1,%2,%3}, [%4];"
                 : "=r"(r0),"=r"(r1),"=r"(r2),"=r"(r3) : "r"(a));
}
__device__ __forceinline__ void ldsm2(unsigned &r0, unsigned &r1, unsigned a) {
    asm volatile("ldmatrix.sync.aligned.m8n8.x2.shared.b16 {%0,%1}, [%2];"
                 : "=r"(r0),"=r"(r1) : "r"(a));
}
__device__ __forceinline__ void mma8(float* c, const unsigned* a, const unsigned* b) {
    asm volatile("mma.sync.aligned.m16n8k8.row.col.f32.tf32.tf32.f32 "
                 "{%0,%1,%2,%3},{%4,%5,%6,%7},{%8,%9},{%0,%1,%2,%3};"
                 : "+f"(c[0]),"+f"(c[1]),"+f"(c[2]),"+f"(c[3])
                 : "r"(a[0]),"r"(a[1]),"r"(a[2]),"r"(a[3]),"r"(b[0]),"r"(b[1]));
}

// ---------------------------------------------------------------------------
// out[M,64] = gelu(X[M,K] @ W[K,64] (+ bias))
// 16 rows x 64 cols per block, 256 threads, K-chunks of 64, reg double-buffer.
// ---------------------------------------------------------------------------
__global__ __launch_bounds__(256) void lowrank_in_kernel(
    const float* __restrict__ X, const float* __restrict__ W,
    const float* __restrict__ bias, float* __restrict__ out, int K)
{
    __shared__ __align__(16) float Xs[16][64];
    __shared__ __align__(16) float Ws[64][68];
    const int tid = threadIdx.x;
    const int tx = tid & 15, ty = tid >> 4;
    const int m0 = blockIdx.x * 16;

    float4 xreg = *(const float4*)&X[(m0 + ty) * K + tx * 4];
    float4 wreg[4];
    #pragma unroll
    for (int ii = 0; ii < 4; ii++) {
        int idx = tid + 256 * ii, r = idx >> 4, c4 = (idx & 15) * 4;
        wreg[ii] = *(const float4*)&W[r * 64 + c4];
    }
    float acc[4] = {};
    const int nk = K >> 6;
    for (int ch = 0; ch < nk; ch++) {
        *(float4*)&Xs[ty][tx * 4] = xreg;
        #pragma unroll
        for (int ii = 0; ii < 4; ii++) {
            int idx = tid + 256 * ii, r = idx >> 4, c4 = (idx & 15) * 4;
            *(float4*)&Ws[r][c4] = wreg[ii];
        }
        __syncthreads();
        if (ch + 1 < nk) {
            int k0 = (ch + 1) << 6;
            xreg = *(const float4*)&X[(m0 + ty) * K + k0 + tx * 4];
            #pragma unroll
            for (int ii = 0; ii < 4; ii++) {
                int idx = tid + 256 * ii, r = idx >> 4, c4 = (idx & 15) * 4;
                wreg[ii] = *(const float4*)&W[(k0 + r) * 64 + c4];
            }
        }
        #pragma unroll
        for (int kk = 0; kk < 64; kk++) {
            float a = Xs[ty][kk];
            float4 bv = *(const float4*)&Ws[kk][tx * 4];
            acc[0] += a * bv.x; acc[1] += a * bv.y; acc[2] += a * bv.z; acc[3] += a * bv.w;
        }
        __syncthreads();
    }
    #pragma unroll
    for (int j = 0; j < 4; j++) {
        float v = acc[j];
        if (bias) v += bias[tx * 4 + j];
        acc[j] = gelu_exact(v);
    }
    *(float4*)&out[(m0 + ty) * 64 + tx * 4] = make_float4(acc[0], acc[1], acc[2], acc[3]);
}

// ---------------------------------------------------------------------------
// qkv = g_h[4096,64] @ w_qkv_b[64,3072]  ->  g_q (x0.125, tf32), g_k (tf32),
// g_vT (transposed [bh][d][n], tf32; staged through SMEM for coalesced writes).
// Block: 32 rows x 128 cols, 256 threads. Each block is entirely q, k, or v.
// ---------------------------------------------------------------------------
__global__ __launch_bounds__(256) void expand_qkv_kernel(const float* __restrict__ Wb)
{
    __shared__ __align__(16) float Hs[32][68];
    __shared__ __align__(16) float Ws[64][132];
    const int tid = threadIdx.x;
    const int tx = tid & 15, ty = tid >> 4;
    const int n0 = blockIdx.x * 128;
    const int m0 = blockIdx.y * 32;
    for (int i = tid; i < 32*64; i += 256) {
        int r = i >> 6, k = i & 63;
        Hs[r][k] = g_h[(m0 + r) * 64 + k];
    }
    for (int i = tid; i < 64*128; i += 256) {
        int k = i >> 7, c = i & 127;
        Ws[k][c] = Wb[k * (3*CDIM) + n0 + c];
    }
    __syncthreads();
    float acc[2][8] = {};
    #pragma unroll
    for (int kk = 0; kk < 64; kk++) {
        float a0 = Hs[ty*2+0][kk];
        float a1 = Hs[ty*2+1][kk];
        float4 b0 = *(const float4*)&Ws[kk][tx*8];
        float4 b1 = *(const float4*)&Ws[kk][tx*8+4];
        float bj[8] = {b0.x, b0.y, b0.z, b0.w, b1.x, b1.y, b1.z, b1.w};
        #pragma unroll
        for (int j = 0; j < 8; j++) { acc[0][j] += a0*bj[j]; acc[1][j] += a1*bj[j]; }
    }
    const int comp = n0 >> 10;     // 0=q 1=k 2=v (uniform per block: 128 | 1024)
    const int bb   = m0 >> 11;
    const int ns0  = m0 & 2047;
    if (comp < 2) {
        #pragma unroll
        for (int i = 0; i < 2; i++) {
            int nseq = ns0 + ty*2 + i;
            #pragma unroll
            for (int j = 0; j < 8; j++) {
                int c    = (n0 + tx*8 + j) & 1023;
                int head = c >> 6, d = c & 63;
                int off  = ((bb*HEADS + head)*NSEQ + nseq)*DH + d;
                if (comp == 0) g_q[off] = tf32r(acc[i][j] * 0.125f);
                else           g_k[off] = tf32r(acc[i][j]);
            }
        }
    } else {
        // stage tile [32 rows][128 cols] and write V^T coalesced
        float* Ts = &Ws[0][0];      // reuse (needs sync: all Ws reads done)
        __syncthreads();
        #pragma unroll
        for (int i = 0; i < 2; i++)
            #pragma unroll
            for (int j = 0; j < 8; j++)
                Ts[(ty*2+i)*133 + tx*8 + j] = tf32r(acc[i][j]);
        __syncthreads();
        #pragma unroll
        for (int ii = 0; ii < 4; ii++) {
            int idx = tid + 256*ii;          // 1024 = 128 (h,d) x 8 n-groups
            int c = idx >> 3, g4 = (idx & 7) * 4;
            int c10  = (n0 + c) & 1023;
            int head = c10 >> 6, d = c10 & 63;
            float4 v = make_float4(Ts[(g4+0)*133 + c], Ts[(g4+1)*133 + c],
                                   Ts[(g4+2)*133 + c], Ts[(g4+3)*133 + c]);
            *(float4*)&g_vT[((size_t)(bb*HEADS + head)*DH + d)*NSEQ + ns0 + g4] = v;
        }
    }
}

// ---------------------------------------------------------------------------
// Flash attention with mma.sync.m16n8k8.tf32.
// Grid (NSEQ/128, B*H), 128 threads (4 warps), warp w owns q-rows [32w,32w+32).
// KV tile 64. Fragments via ldmatrix.b16 (8x8 b16 == 8x4 tf32).
// ---------------------------------------------------------------------------
#define FLD 68
#define FLASH_SMEM ((128 + 64 + 64 + 128) * FLD * 4)

__global__ __launch_bounds__(128) void flash_mma_kernel()
{
    extern __shared__ __align__(16) float sm[];
    float* Qs  = sm;                   // [128][FLD]
    float* Ks  = Qs  + 128*FLD;        // [64][FLD]   rows = kv col, cols = d
    float* Vst = Ks  + 64*FLD;         // [64][FLD]   rows = d,      cols = kv
    float* Ps  = Vst + 64*FLD;         // [128][FLD]  warp-private 32-row strips

    const int tid  = threadIdx.x;
    const int lane = tid & 31, w = tid >> 5;
    const int bh = blockIdx.y;
    const int q0 = blockIdx.x * 128;
    const int b = bh >> 4, h = bh & 15;

    const float* Qg  = g_q  + ((size_t)bh * NSEQ + q0) * DH;
    const float* Kg  = g_k  + (size_t)bh * NSEQ * DH;
    const float* VTg = g_vT + (size_t)bh * DH * NSEQ;

    #pragma unroll
    for (int it = 0; it < 16; it++) {
        int i = tid + 128 * it, r = i >> 4, c4 = (i & 15) * 4;
        *(float4*)&Qs[r*FLD + c4] = *(const float4*)&Qg[r*DH + c4];
    }

    // ldmatrix per-lane offsets (bytes)
    const int lr = lane & 7, lm = lane >> 3;
    const unsigned aOff = (unsigned)((((lm & 1) * 8 + lr) * FLD + (lm >> 1) * 4) * 4);
    const unsigned bOff = (unsigned)((lr * FLD + ((lm & 1) * 4)) * 4);
    const unsigned qsA = (unsigned)__cvta_generic_to_shared(Qs)  + aOff;
    const unsigned ksB = (unsigned)__cvta_generic_to_shared(Ks)  + bOff;
    const unsigned vtB = (unsigned)__cvta_generic_to_shared(Vst) + bOff;
    const unsigned psA = (unsigned)__cvta_generic_to_shared(Ps)  + aOff;

    float o[2][8][4];
    float mrow[2][2], lrow[2][2];
    #pragma unroll
    for (int mt = 0; mt < 2; mt++) {
        mrow[mt][0] = mrow[mt][1] = -1e30f;
        lrow[mt][0] = lrow[mt][1] = 0.f;
        #pragma unroll
        for (int j = 0; j < 8; j++)
            o[mt][j][0] = o[mt][j][1] = o[mt][j][2] = o[mt][j][3] = 0.f;
    }

    for (int t = 0; t < NSEQ/64; t++) {
        __syncthreads();   // all warps done with previous Ks/Vst
        const float* Kt  = Kg  + (size_t)t * 64 * DH;
        #pragma unroll
        for (int it = 0; it < 8; it++) {
            int i = tid + 128 * it, r = i >> 4, c4 = (i & 15) * 4;
            *(float4*)&Ks[r*FLD + c4]  = *(const float4*)&Kt[r*DH + c4];
            *(float4*)&Vst[r*FLD + c4] = *(const float4*)&VTg[(size_t)r*NSEQ + t*64 + c4];
        }
        __syncthreads();

        // ---- S = Q K^T  (per warp: 2 m-tiles x 8 n-tiles) ----
        float s[2][8][4];
        #pragma unroll
        for (int mt = 0; mt < 2; mt++)
            #pragma unroll
            for (int j = 0; j < 8; j++)
                s[mt][j][0] = s[mt][j][1] = s[mt][j][2] = s[mt][j][3] = 0.f;

        #pragma unroll
        for (int ks = 0; ks < 8; ks++) {
            const int kk = ks * 8;
            unsigned bf[8][2];
            #pragma unroll
            for (int j = 0; j < 8; j++)
                ldsm2(bf[j][0], bf[j][1], ksB + (unsigned)((j*8*FLD + kk) * 4));
            #pragma unroll
            for (int mt = 0; mt < 2; mt++) {
                unsigned af[4];
                ldsm4(af[0], af[1], af[2], af[3],
                      qsA + (unsigned)(((w*32 + mt*16)*FLD + kk) * 4));
                #pragma unroll
                for (int j = 0; j < 8; j++) mma8(s[mt][j], af, bf[j]);
            }
        }

        // ---- online softmax ----
        #pragma unroll
        for (int mt = 0; mt < 2; mt++) {
            float mxl = -1e30f, mxh = -1e30f;
            #pragma unroll
            for (int j = 0; j < 8; j++) {
                mxl = fmaxf(mxl, fmaxf(s[mt][j][0], s[mt][j][1]));
                mxh = fmaxf(mxh, fmaxf(s[mt][j][2], s[mt][j][3]));
            }
            mxl = fmaxf(mxl, __shfl_xor_sync(0xffffffffu, mxl, 1));
            mxl = fmaxf(mxl, __shfl_xor_sync(0xffffffffu, mxl, 2));
            mxh = fmaxf(mxh, __shfl_xor_sync(0xffffffffu, mxh, 1));
            mxh = fmaxf(mxh, __shfl_xor_sync(0xffffffffu, mxh, 2));
            float mln = fmaxf(mrow[mt][0], mxl);
            float mhn = fmaxf(mrow[mt][1], mxh);
            float al = __expf(mrow[mt][0] - mln);
            float ah = __expf(mrow[mt][1] - mhn);
            mrow[mt][0] = mln; mrow[mt][1] = mhn;
            float sl = 0.f, sh = 0.f;
            float* PsL = &Ps[(w*32 + mt*16 + (lane >> 2))*FLD + (lane & 3)*2];
            float* PsH = PsL + 8*FLD;
            #pragma unroll
            for (int j = 0; j < 8; j++) {
                float p0 = tf32r(__expf(s[mt][j][0] - mln));
                float p1 = tf32r(__expf(s[mt][j][1] - mln));
                float p2 = tf32r(__expf(s[mt][j][2] - mhn));
                float p3 = tf32r(__expf(s[mt][j][3] - mhn));
                sl += p0 + p1; sh += p2 + p3;
                *(float2*)&PsL[j*8] = make_float2(p0, p1);
                *(float2*)&PsH[j*8] = make_float2(p2, p3);
            }
            sl += __shfl_xor_sync(0xffffffffu, sl, 1);
            sl += __shfl_xor_sync(0xffffffffu, sl, 2);
            sh += __shfl_xor_sync(0xffffffffu, sh, 1);
            sh += __shfl_xor_sync(0xffffffffu, sh, 2);
            lrow[mt][0] = lrow[mt][0]*al + sl;
            lrow[mt][1] = lrow[mt][1]*ah + sh;
            #pragma unroll
            for (int j = 0; j < 8; j++) {
                o[mt][j][0] *= al; o[mt][j][1] *= al;
                o[mt][j][2] *= ah; o[mt][j][3] *= ah;
            }
        }
        __syncwarp();

        // ---- O += P V ----
        #pragma unroll
        for (int ks = 0; ks < 8; ks++) {
            const int kc = ks * 8;
            unsigned bf[8][2];
            #pragma unroll
            for (int jd = 0; jd < 8; jd++)
                ldsm2(bf[jd][0], bf[jd][1], vtB + (unsigned)((jd*8*FLD + kc) * 4));
            #pragma unroll
            for (int mt = 0; mt < 2; mt++) {
                unsigned af[4];
                ldsm4(af[0], af[1], af[2], af[3],
                      psA + (unsigned)(((w*32 + mt*16)*FLD + kc) * 4));
                #pragma unroll
                for (int jd = 0; jd < 8; jd++) mma8(o[mt][jd], af, bf[jd]);
            }
        }
    }

    // ---- epilogue ----
    #pragma unroll
    for (int mt = 0; mt < 2; mt++) {
        float il = 1.0f / lrow[mt][0], ih = 1.0f / lrow[mt][1];
        int rowl = q0 + w*32 + mt*16 + (lane >> 2);
        size_t basel = ((size_t)(b*NSEQ + rowl))*CDIM + h*DH + (lane & 3)*2;
        size_t baseh = basel + (size_t)8*CDIM;
        #pragma unroll
        for (int j = 0; j < 8; j++) {
            *(float2*)&g_attn[basel + j*8] = make_float2(o[mt][j][0]*il, o[mt][j][1]*il);
            *(float2*)&g_attn[baseh + j*8] = make_float2(o[mt][j][2]*ih, o[mt][j][3]*ih);
        }
    }
}

// ---------------------------------------------------------------------------
// y[M,1024] = g_h2[M,64] @ w_proj_b[64,1024] + b_proj_b
// ---------------------------------------------------------------------------
__global__ __launch_bounds__(256) void lowrank_out_kernel(
    const float* __restrict__ Wb, const float* __restrict__ bias,
    float* __restrict__ out)
{
    __shared__ __align__(16) float Hs[32][68];
    __shared__ __align__(16) float Ws[64][132];
    const int tid = threadIdx.x;
    const int tx = tid & 15, ty = tid >> 4;
    const int n0 = blockIdx.x * 128;
    const int m0 = blockIdx.y * 32;
    for (int i = tid; i < 32*64; i += 256) {
        int r = i >> 6, k = i & 63;
        Hs[r][k] = g_h2[(m0 + r) * 64 + k];
    }
    for (int i = tid; i < 64*128; i += 256) {
        int k = i >> 7, c = i & 127;
        Ws[k][c] = Wb[k * CDIM + n0 + c];
    }
    __syncthreads();
    float acc[2][8] = {};
    #pragma unroll
    for (int kk = 0; kk < 64; kk++) {
        float a0 = Hs[ty*2+0][kk];
        float a1 = Hs[ty*2+1][kk];
        float4 b0 = *(const float4*)&Ws[kk][tx*8];
        float4 b1 = *(const float4*)&Ws[kk][tx*8+4];
        float bj[8] = {b0.x, b0.y, b0.z, b0.w, b1.x, b1.y, b1.z, b1.w};
        #pragma unroll
        for (int j = 0; j < 8; j++) { acc[0][j] += a0*bj[j]; acc[1][j] += a1*bj[j]; }
    }
    float4 bv0 = *(const float4*)&bias[n0 + tx*8];
    float4 bv1 = *(const float4*)&bias[n0 + tx*8 + 4];
    #pragma unroll
    for (int i = 0; i < 2; i++) {
        size_t base = (size_t)(m0 + ty*2 + i)*CDIM + n0 + tx*8;
        *(float4*)&out[base]     = make_float4(acc[i][0]+bv0.x, acc[i][1]+bv0.y, acc[i][2]+bv0.z, acc[i][3]+bv0.w);
        *(float4*)&out[base + 4] = make_float4(acc[i][4]+bv1.x, acc[i][5]+bv1.y, acc[i][6]+bv1.z, acc[i][7]+bv1.w);
    }
}

// ---------------------------------------------------------------------------
extern "C" void kernel_launch(void* const* d_in, const int* in_sizes, int n_in,
                              void* d_out, int out_size)
{
    const float* x        = (const float*)d_in[0];
    const float* w_qkv_a  = (const float*)d_in[1];
    const float* w_qkv_b  = (const float*)d_in[2];
    const float* w_proj_a = (const float*)d_in[3];
    const float* b_proj_a = (const float*)d_in[4];
    const float* w_proj_b = (const float*)d_in[5];
    const float* b_proj_b = (const float*)d_in[6];
    float* out = (float*)d_out;

    float *ph = nullptr, *ph2 = nullptr, *pattn = nullptr;
    cudaGetSymbolAddress((void**)&ph,    g_h);
    cudaGetSymbolAddress((void**)&ph2,   g_h2);
    cudaGetSymbolAddress((void**)&pattn, g_attn);

    static bool attr_set = false;
    if (!attr_set) {
        cudaFuncSetAttribute(flash_mma_kernel,
                             cudaFuncAttributeMaxDynamicSharedMemorySize, FLASH_SMEM);
        attr_set = true;
    }

    // 1. h = gelu(x @ w_qkv_a)                    [4096,64]
    lowrank_in_kernel<<<MTOT/16, 256>>>(x, w_qkv_a, nullptr, ph, CDIM);
    // 2. qkv = h @ w_qkv_b -> q (scaled, tf32), k (tf32), vT (tf32, transposed)
    expand_qkv_kernel<<<dim3(3*CDIM/128, MTOT/32), 256>>>(w_qkv_b);
    // 3. tensor-core flash attention -> g_attn [B,N,C]
    flash_mma_kernel<<<dim3(NSEQ/128, BD*HEADS), 128, FLASH_SMEM>>>();
    // 4. h2 = gelu(attn @ w_proj_a + b_proj_a)    [4096,64]
    lowrank_in_kernel<<<MTOT/16, 256>>>(pattn, w_proj_a, b_proj_a, ph2, CDIM);
    // 5. y = h2 @ w_proj_b + b_proj_b             [4096,1024]
    lowrank_out_kernel<<<dim3(CDIM/128, MTOT/32), 256>>>(w_proj_b, b_proj_b, out);
}

// round 5
// speedup vs baseline: 3.5927x; 1.4463x over previous
#include <cuda_runtime.h>
#include <cuda_fp16.h>
#include <math.h>

#define BD    2
#define NSEQ  2048
#define CDIM  1024
#define RANK  64
#define HEADS 16
#define DH    64
#define MTOT  (BD*NSEQ)   // 4096

// Scratch (device globals: no allocation allowed in kernel_launch)
__device__ float  g_h   [MTOT*RANK];            // gelu(x @ w_qkv_a)
__device__ __half g_qh  [BD*HEADS*NSEQ*DH];     // scaled Q fp16 [bh][n][d]
__device__ __half g_kh  [BD*HEADS*NSEQ*DH];     // K fp16       [bh][n][d]
__device__ __half g_vTh [BD*HEADS*DH*NSEQ];     // V^T fp16     [bh][d][n]
__device__ float  g_attn[MTOT*CDIM];            // attention out [B,N,C]
__device__ float  g_h2  [MTOT*RANK];            // gelu(attn @ w_proj_a + b)

__device__ __forceinline__ float gelu_exact(float v) {
    return 0.5f * v * (1.0f + erff(v * 0.70710678118654752440f));
}
__device__ __forceinline__ unsigned pack2(float a, float b) {
    __half2 h = __floats2half2_rn(a, b);
    return *(unsigned*)&h;
}
__device__ __forceinline__ void ldsm4(unsigned &r0, unsigned &r1, unsigned &r2, unsigned &r3, unsigned a) {
    asm volatile("ldmatrix.sync.aligned.m8n8.x4.shared.b16 {%0,%1,%2,%3}, [%4];"
                 : "=r"(r0),"=r"(r1),"=r"(r2),"=r"(r3) : "r"(a));
}
__device__ __forceinline__ void ldsm2(unsigned &r0, unsigned &r1, unsigned a) {
    asm volatile("ldmatrix.sync.aligned.m8n8.x2.shared.b16 {%0,%1}, [%2];"
                 : "=r"(r0),"=r"(r1) : "r"(a));
}
__device__ __forceinline__ void mma16(float* c, const unsigned* a, const unsigned* b) {
    asm volatile("mma.sync.aligned.m16n8k16.row.col.f32.f16.f16.f32 "
                 "{%0,%1,%2,%3},{%4,%5,%6,%7},{%8,%9},{%0,%1,%2,%3};"
                 : "+f"(c[0]),"+f"(c[1]),"+f"(c[2]),"+f"(c[3])
                 : "r"(a[0]),"r"(a[1]),"r"(a[2]),"r"(a[3]),"r"(b[0]),"r"(b[1]));
}

// ---------------------------------------------------------------------------
// out[M,64] = gelu(X[M,K] @ W[K,64] (+ bias))
// 128 threads, 16-row tile, 2 rows x 4 cols per thread, K-chunks of 64,
// register double-buffer. SMEM bytes/FMA ~= 3.
// ---------------------------------------------------------------------------
__global__ __launch_bounds__(128) void lowrank_in_kernel(
    const float* __restrict__ X, const float* __restrict__ W,
    const float* __restrict__ bias, float* __restrict__ out, int K)
{
    __shared__ __align__(16) float Xs[16][68];
    __shared__ __align__(16) float Ws[64][68];
    const int tid = threadIdx.x;
    const int tx = tid & 15, ty = tid >> 4;   // ty 0..7 -> 2 rows each
    const int m0 = blockIdx.x * 16;

    float4 xreg[2], wreg[8];
    #pragma unroll
    for (int ii = 0; ii < 2; ii++) {
        int idx = tid + 128 * ii, r = idx >> 4, c4 = (idx & 15) * 4;
        xreg[ii] = *(const float4*)&X[(m0 + r) * K + c4];
    }
    #pragma unroll
    for (int ii = 0; ii < 8; ii++) {
        int idx = tid + 128 * ii, r = idx >> 4, c4 = (idx & 15) * 4;
        wreg[ii] = *(const float4*)&W[r * 64 + c4];
    }
    float acc[2][4] = {};
    const int nk = K >> 6;
    for (int ch = 0; ch < nk; ch++) {
        #pragma unroll
        for (int ii = 0; ii < 2; ii++) {
            int idx = tid + 128 * ii, r = idx >> 4, c4 = (idx & 15) * 4;
            *(float4*)&Xs[r][c4] = xreg[ii];
        }
        #pragma unroll
        for (int ii = 0; ii < 8; ii++) {
            int idx = tid + 128 * ii, r = idx >> 4, c4 = (idx & 15) * 4;
            *(float4*)&Ws[r][c4] = wreg[ii];
        }
        __syncthreads();
        if (ch + 1 < nk) {
            int k0 = (ch + 1) << 6;
            #pragma unroll
            for (int ii = 0; ii < 2; ii++) {
                int idx = tid + 128 * ii, r = idx >> 4, c4 = (idx & 15) * 4;
                xreg[ii] = *(const float4*)&X[(m0 + r) * K + k0 + c4];
            }
            #pragma unroll
            for (int ii = 0; ii < 8; ii++) {
                int idx = tid + 128 * ii, r = idx >> 4, c4 = (idx & 15) * 4;
                wreg[ii] = *(const float4*)&W[(k0 + r) * 64 + c4];
            }
        }
        #pragma unroll
        for (int kk = 0; kk < 64; kk++) {
            float a0 = Xs[ty*2+0][kk];
            float a1 = Xs[ty*2+1][kk];
            float4 bv = *(const float4*)&Ws[kk][tx * 4];
            acc[0][0] += a0*bv.x; acc[0][1] += a0*bv.y; acc[0][2] += a0*bv.z; acc[0][3] += a0*bv.w;
            acc[1][0] += a1*bv.x; acc[1][1] += a1*bv.y; acc[1][2] += a1*bv.z; acc[1][3] += a1*bv.w;
        }
        __syncthreads();
    }
    #pragma unroll
    for (int i = 0; i < 2; i++) {
        float4 r;
        float* pr = (float*)&r;
        #pragma unroll
        for (int j = 0; j < 4; j++) {
            float v = acc[i][j];
            if (bias) v += bias[tx * 4 + j];
            pr[j] = gelu_exact(v);
        }
        *(float4*)&out[(m0 + ty*2 + i) * 64 + tx * 4] = r;
    }
}

// ---------------------------------------------------------------------------
// qkv = g_h[4096,64] @ w_qkv_b[64,3072] -> g_qh (x0.125), g_kh, g_vTh (fp16,
// V transposed [bh][d][n] via SMEM staging). 32 rows x 128 cols per block.
// ---------------------------------------------------------------------------
__global__ __launch_bounds__(256) void expand_qkv_kernel(const float* __restrict__ Wb)
{
    __shared__ __align__(16) float Hs[32][68];
    __shared__ __align__(16) float Ws[64][132];
    const int tid = threadIdx.x;
    const int tx = tid & 15, ty = tid >> 4;
    const int n0 = blockIdx.x * 128;
    const int m0 = blockIdx.y * 32;
    for (int i = tid; i < 32*64; i += 256) {
        int r = i >> 6, k = i & 63;
        Hs[r][k] = g_h[(m0 + r) * 64 + k];
    }
    for (int i = tid; i < 64*128; i += 256) {
        int k = i >> 7, c = i & 127;
        Ws[k][c] = Wb[k * (3*CDIM) + n0 + c];
    }
    __syncthreads();
    float acc[2][8] = {};
    #pragma unroll
    for (int kk = 0; kk < 64; kk++) {
        float a0 = Hs[ty*2+0][kk];
        float a1 = Hs[ty*2+1][kk];
        float4 b0 = *(const float4*)&Ws[kk][tx*8];
        float4 b1 = *(const float4*)&Ws[kk][tx*8+4];
        float bj[8] = {b0.x, b0.y, b0.z, b0.w, b1.x, b1.y, b1.z, b1.w};
        #pragma unroll
        for (int j = 0; j < 8; j++) { acc[0][j] += a0*bj[j]; acc[1][j] += a1*bj[j]; }
    }
    const int comp = n0 >> 10;     // 0=q 1=k 2=v (uniform per block)
    const int bb   = m0 >> 11;
    const int ns0  = m0 & 2047;
    if (comp < 2) {
        const float sc = (comp == 0) ? 0.125f : 1.0f;
        __half* dst = (comp == 0) ? g_qh : g_kh;
        #pragma unroll
        for (int i = 0; i < 2; i++) {
            int nseq = ns0 + ty*2 + i;
            int c    = (n0 + tx*8) & 1023;
            int head = c >> 6, d = c & 63;
            size_t off = ((size_t)(bb*HEADS + head)*NSEQ + nseq)*DH + d;
            uint4 u;
            u.x = pack2(acc[i][0]*sc, acc[i][1]*sc);
            u.y = pack2(acc[i][2]*sc, acc[i][3]*sc);
            u.z = pack2(acc[i][4]*sc, acc[i][5]*sc);
            u.w = pack2(acc[i][6]*sc, acc[i][7]*sc);
            *(uint4*)&dst[off] = u;
        }
    } else {
        // stage tile [32 n][128 c] as float, then write V^T fp16 coalesced
        float* Ts = &Ws[0][0];
        __syncthreads();
        #pragma unroll
        for (int i = 0; i < 2; i++)
            #pragma unroll
            for (int j = 0; j < 8; j++)
                Ts[(ty*2+i)*133 + tx*8 + j] = acc[i][j];
        __syncthreads();
        #pragma unroll
        for (int ii = 0; ii < 4; ii++) {
            int idx = tid + 256*ii;          // 1024 = 128 cols x 8 n-groups of 4
            int c = idx >> 3, g4 = (idx & 7) * 4;
            int c10  = (n0 + c) & 1023;
            int head = c10 >> 6, d = c10 & 63;
            uint2 u;
            u.x = pack2(Ts[(g4+0)*133 + c], Ts[(g4+1)*133 + c]);
            u.y = pack2(Ts[(g4+2)*133 + c], Ts[(g4+3)*133 + c]);
            *(uint2*)&g_vTh[((size_t)(bb*HEADS + head)*DH + d)*NSEQ + ns0 + g4] = u;
        }
    }
}

// ---------------------------------------------------------------------------
// Flash attention with fp16 mma.m16n8k16, fp32 accum.
// Grid (NSEQ/128, B*H), 128 threads (4 warps), warp w owns q-rows [32w,32w+32).
// KV tile 64. SMEM tiles fp16, lead dim 72 halves (144 B, conflict-free ldmatrix).
// ---------------------------------------------------------------------------
#define LDH 72
#define FLASH_SMEM ((128 + 64 + 64 + 128) * LDH * 2)

__global__ __launch_bounds__(128) void flash_mma_kernel()
{
    extern __shared__ __align__(16) __half smh[];
    __half* Qs  = smh;                  // [128][LDH] rows=q,  cols=d
    __half* Ks  = Qs  + 128*LDH;        // [64][LDH]  rows=kv, cols=d
    __half* Vst = Ks  + 64*LDH;         // [64][LDH]  rows=d,  cols=kv
    __half* Ps  = Vst + 64*LDH;         // [128][LDH] rows=q,  cols=kv (warp-private strips)

    const int tid  = threadIdx.x;
    const int lane = tid & 31, w = tid >> 5;
    const int bh = blockIdx.y;
    const int q0 = blockIdx.x * 128;
    const int b = bh >> 4, h = bh & 15;

    const __half* Qg  = g_qh  + ((size_t)bh * NSEQ + q0) * DH;
    const __half* Kg  = g_kh  + (size_t)bh * NSEQ * DH;
    const __half* VTg = g_vTh + (size_t)bh * DH * NSEQ;

    #pragma unroll
    for (int it = 0; it < 8; it++) {
        int i = tid + 128 * it, r = i >> 3, c8 = (i & 7) * 8;
        *(uint4*)&Qs[r*LDH + c8] = *(const uint4*)&Qg[r*DH + c8];
    }

    // ldmatrix per-lane byte offsets
    const unsigned aOff = (unsigned)((((lane & 15) * LDH) + (lane >> 4) * 8) * 2);
    const unsigned bOff = (unsigned)((((lane & 7) * LDH) + ((lane >> 3) & 1) * 8) * 2);
    const unsigned qsA = (unsigned)__cvta_generic_to_shared(Qs)  + aOff;
    const unsigned ksB = (unsigned)__cvta_generic_to_shared(Ks)  + bOff;
    const unsigned vtB = (unsigned)__cvta_generic_to_shared(Vst) + bOff;
    const unsigned psA = (unsigned)__cvta_generic_to_shared(Ps)  + aOff;

    float o[2][8][4];
    float mrow[2][2], lrow[2][2];
    #pragma unroll
    for (int mt = 0; mt < 2; mt++) {
        mrow[mt][0] = mrow[mt][1] = -1e30f;
        lrow[mt][0] = lrow[mt][1] = 0.f;
        #pragma unroll
        for (int j = 0; j < 8; j++)
            o[mt][j][0] = o[mt][j][1] = o[mt][j][2] = o[mt][j][3] = 0.f;
    }

    for (int t = 0; t < NSEQ/64; t++) {
        __syncthreads();   // all warps done with previous Ks/Vst
        const __half* Kt = Kg + (size_t)t * 64 * DH;
        #pragma unroll
        for (int it = 0; it < 4; it++) {
            int i = tid + 128 * it, r = i >> 3, c8 = (i & 7) * 8;
            *(uint4*)&Ks[r*LDH + c8]  = *(const uint4*)&Kt[r*DH + c8];
            *(uint4*)&Vst[r*LDH + c8] = *(const uint4*)&VTg[(size_t)r*NSEQ + t*64 + c8];
        }
        __syncthreads();

        // ---- S = Q K^T  (per warp: 2 m-tiles x 8 n-tiles, 4 k-steps) ----
        float s[2][8][4];
        #pragma unroll
        for (int mt = 0; mt < 2; mt++)
            #pragma unroll
            for (int j = 0; j < 8; j++)
                s[mt][j][0] = s[mt][j][1] = s[mt][j][2] = s[mt][j][3] = 0.f;

        #pragma unroll
        for (int ks = 0; ks < 4; ks++) {
            const int kk = ks * 16;
            unsigned bf[8][2];
            #pragma unroll
            for (int j = 0; j < 8; j++)
                ldsm2(bf[j][0], bf[j][1], ksB + (unsigned)((j*8*LDH + kk) * 2));
            #pragma unroll
            for (int mt = 0; mt < 2; mt++) {
                unsigned af[4];
                ldsm4(af[0], af[1], af[2], af[3],
                      qsA + (unsigned)(((w*32 + mt*16)*LDH + kk) * 2));
                #pragma unroll
                for (int j = 0; j < 8; j++) mma16(s[mt][j], af, bf[j]);
            }
        }

        // ---- online softmax (fp32 state; P rounded to fp16 consistently) ----
        #pragma unroll
        for (int mt = 0; mt < 2; mt++) {
            float mxl = -1e30f, mxh = -1e30f;
            #pragma unroll
            for (int j = 0; j < 8; j++) {
                mxl = fmaxf(mxl, fmaxf(s[mt][j][0], s[mt][j][1]));
                mxh = fmaxf(mxh, fmaxf(s[mt][j][2], s[mt][j][3]));
            }
            mxl = fmaxf(mxl, __shfl_xor_sync(0xffffffffu, mxl, 1));
            mxl = fmaxf(mxl, __shfl_xor_sync(0xffffffffu, mxl, 2));
            mxh = fmaxf(mxh, __shfl_xor_sync(0xffffffffu, mxh, 1));
            mxh = fmaxf(mxh, __shfl_xor_sync(0xffffffffu, mxh, 2));
            float mln = fmaxf(mrow[mt][0], mxl);
            float mhn = fmaxf(mrow[mt][1], mxh);
            float al = __expf(mrow[mt][0] - mln);
            float ah = __expf(mrow[mt][1] - mhn);
            mrow[mt][0] = mln; mrow[mt][1] = mhn;
            float sl = 0.f, sh = 0.f;
            __half* PsL = &Ps[(w*32 + mt*16 + (lane >> 2))*LDH + (lane & 3)*2];
            __half* PsH = PsL + 8*LDH;
            #pragma unroll
            for (int j = 0; j < 8; j++) {
                __half2 hl = __floats2half2_rn(__expf(s[mt][j][0] - mln),
                                               __expf(s[mt][j][1] - mln));
                __half2 hh = __floats2half2_rn(__expf(s[mt][j][2] - mhn),
                                               __expf(s[mt][j][3] - mhn));
                float2 fl = __half22float2(hl), fh = __half22float2(hh);
                sl += fl.x + fl.y; sh += fh.x + fh.y;
                *(__half2*)&PsL[j*8] = hl;
                *(__half2*)&PsH[j*8] = hh;
            }
            sl += __shfl_xor_sync(0xffffffffu, sl, 1);
            sl += __shfl_xor_sync(0xffffffffu, sl, 2);
            sh += __shfl_xor_sync(0xffffffffu, sh, 1);
            sh += __shfl_xor_sync(0xffffffffu, sh, 2);
            lrow[mt][0] = lrow[mt][0]*al + sl;
            lrow[mt][1] = lrow[mt][1]*ah + sh;
            #pragma unroll
            for (int j = 0; j < 8; j++) {
                o[mt][j][0] *= al; o[mt][j][1] *= al;
                o[mt][j][2] *= ah; o[mt][j][3] *= ah;
            }
        }
        __syncwarp();

        // ---- O += P V  (A = Ps rows q x kv, B = Vst rows d x kv) ----
        #pragma unroll
        for (int ks = 0; ks < 4; ks++) {
            const int kc = ks * 16;
            unsigned bf[8][2];
            #pragma unroll
            for (int jd = 0; jd < 8; jd++)
                ldsm2(bf[jd][0], bf[jd][1], vtB + (unsigned)((jd*8*LDH + kc) * 2));
            #pragma unroll
            for (int mt = 0; mt < 2; mt++) {
                unsigned af[4];
                ldsm4(af[0], af[1], af[2], af[3],
                      psA + (unsigned)(((w*32 + mt*16)*LDH + kc) * 2));
                #pragma unroll
                for (int jd = 0; jd < 8; jd++) mma16(o[mt][jd], af, bf[jd]);
            }
        }
    }

    // ---- epilogue (fp32 out to [B,N,C]) ----
    #pragma unroll
    for (int mt = 0; mt < 2; mt++) {
        float il = 1.0f / lrow[mt][0], ih = 1.0f / lrow[mt][1];
        int rowl = q0 + w*32 + mt*16 + (lane >> 2);
        size_t basel = ((size_t)(b*NSEQ + rowl))*CDIM + h*DH + (lane & 3)*2;
        size_t baseh = basel + (size_t)8*CDIM;
        #pragma unroll
        for (int j = 0; j < 8; j++) {
            *(float2*)&g_attn[basel + j*8] = make_float2(o[mt][j][0]*il, o[mt][j][1]*il);
            *(float2*)&g_attn[baseh + j*8] = make_float2(o[mt][j][2]*ih, o[mt][j][3]*ih);
        }
    }
}

// ---------------------------------------------------------------------------
// y[M,1024] = g_h2[M,64] @ w_proj_b[64,1024] + b_proj_b
// ---------------------------------------------------------------------------
__global__ __launch_bounds__(256) void lowrank_out_kernel(
    const float* __restrict__ Wb, const float* __restrict__ bias,
    float* __restrict__ out)
{
    __shared__ __align__(16) float Hs[32][68];
    __shared__ __align__(16) float Ws[64][132];
    const int tid = threadIdx.x;
    const int tx = tid & 15, ty = tid >> 4;
    const int n0 = blockIdx.x * 128;
    const int m0 = blockIdx.y * 32;
    for (int i = tid; i < 32*64; i += 256) {
        int r = i >> 6, k = i & 63;
        Hs[r][k] = g_h2[(m0 + r) * 64 + k];
    }
    for (int i = tid; i < 64*128; i += 256) {
        int k = i >> 7, c = i & 127;
        Ws[k][c] = Wb[k * CDIM + n0 + c];
    }
    __syncthreads();
    float acc[2][8] = {};
    #pragma unroll
    for (int kk = 0; kk < 64; kk++) {
        float a0 = Hs[ty*2+0][kk];
        float a1 = Hs[ty*2+1][kk];
        float4 b0 = *(const float4*)&Ws[kk][tx*8];
        float4 b1 = *(const float4*)&Ws[kk][tx*8+4];
        float bj[8] = {b0.x, b0.y, b0.z, b0.w, b1.x, b1.y, b1.z, b1.w};
        #pragma unroll
        for (int j = 0; j < 8; j++) { acc[0][j] += a0*bj[j]; acc[1][j] += a1*bj[j]; }
    }
    float4 bv0 = *(const float4*)&bias[n0 + tx*8];
    float4 bv1 = *(const float4*)&bias[n0 + tx*8 + 4];
    #pragma unroll
    for (int i = 0; i < 2; i++) {
        size_t base = (size_t)(m0 + ty*2 + i)*CDIM + n0 + tx*8;
        *(float4*)&out[base]     = make_float4(acc[i][0]+bv0.x, acc[i][1]+bv0.y, acc[i][2]+bv0.z, acc[i][3]+bv0.w);
        *(float4*)&out[base + 4] = make_float4(acc[i][4]+bv1.x, acc[i][5]+bv1.y, acc[i][6]+bv1.z, acc[i][7]+bv1.w);
    }
}

// ---------------------------------------------------------------------------
extern "C" void kernel_launch(void* const* d_in, const int* in_sizes, int n_in,
                              void* d_out, int out_size)
{
    const float* x        = (const float*)d_in[0];
    const float* w_qkv_a  = (const float*)d_in[1];
    const float* w_qkv_b  = (const float*)d_in[2];
    const float* w_proj_a = (const float*)d_in[3];
    const float* b_proj_a = (const float*)d_in[4];
    const float* w_proj_b = (const float*)d_in[5];
    const float* b_proj_b = (const float*)d_in[6];
    float* out = (float*)d_out;

    float *ph = nullptr, *ph2 = nullptr, *pattn = nullptr;
    cudaGetSymbolAddress((void**)&ph,    g_h);
    cudaGetSymbolAddress((void**)&ph2,   g_h2);
    cudaGetSymbolAddress((void**)&pattn, g_attn);

    static bool attr_set = false;
    if (!attr_set) {
        cudaFuncSetAttribute(flash_mma_kernel,
                             cudaFuncAttributeMaxDynamicSharedMemorySize, FLASH_SMEM);
        attr_set = true;
    }

    // 1. h = gelu(x @ w_qkv_a)                    [4096,64]
    lowrank_in_kernel<<<MTOT/16, 128>>>(x, w_qkv_a, nullptr, ph, CDIM);
    // 2. qkv = h @ w_qkv_b -> q (scaled), k, vT   (all fp16)
    expand_qkv_kernel<<<dim3(3*CDIM/128, MTOT/32), 256>>>(w_qkv_b);
    // 3. fp16 tensor-core flash attention -> g_attn [B,N,C]
    flash_mma_kernel<<<dim3(NSEQ/128, BD*HEADS), 128, FLASH_SMEM>>>();
    // 4. h2 = gelu(attn @ w_proj_a + b_proj_a)    [4096,64]
    lowrank_in_kernel<<<MTOT/16, 128>>>(pattn, w_proj_a, b_proj_a, ph2, CDIM);
    // 5. y = h2 @ w_proj_b + b_proj_b             [4096,1024]
    lowrank_out_kernel<<<dim3(CDIM/128, MTOT/32), 256>>>(w_proj_b, b_proj_b, out);
}

// round 6
// speedup vs baseline: 4.4752x; 1.2456x over previous
#include <cuda_runtime.h>
#include <cuda_fp16.h>
#include <math.h>

#define BD    2
#define NSEQ  2048
#define CDIM  1024
#define RANK  64
#define HEADS 16
#define DH    64
#define MTOT  (BD*NSEQ)   // 4096

// Scratch (device globals: no allocation allowed in kernel_launch)
__device__ float  g_h   [MTOT*RANK];            // gelu(x @ w_qkv_a)
__device__ __half g_qh  [BD*HEADS*NSEQ*DH];     // Q * 0.125*log2e, fp16 [bh][n][d]
__device__ __half g_kh  [BD*HEADS*NSEQ*DH];     // K fp16               [bh][n][d]
__device__ __half g_vTh [BD*HEADS*DH*NSEQ];     // V^T fp16             [bh][d][n]
__device__ float  g_attn[MTOT*CDIM];            // attention out [B,N,C]
__device__ float  g_h2  [MTOT*RANK];            // gelu(attn @ w_proj_a + b)

__device__ __forceinline__ float gelu_exact(float v) {
    return 0.5f * v * (1.0f + erff(v * 0.70710678118654752440f));
}
__device__ __forceinline__ unsigned pack2(float a, float b) {
    __half2 h = __floats2half2_rn(a, b);
    return *(unsigned*)&h;
}
__device__ __forceinline__ void ldsm4(unsigned &r0, unsigned &r1, unsigned &r2, unsigned &r3, unsigned a) {
    asm volatile("ldmatrix.sync.aligned.m8n8.x4.shared.b16 {%0,%1,%2,%3}, [%4];"
                 : "=r"(r0),"=r"(r1),"=r"(r2),"=r"(r3) : "r"(a));
}
__device__ __forceinline__ void ldsm2(unsigned &r0, unsigned &r1, unsigned a) {
    asm volatile("ldmatrix.sync.aligned.m8n8.x2.shared.b16 {%0,%1}, [%2];"
                 : "=r"(r0),"=r"(r1) : "r"(a));
}
__device__ __forceinline__ void mma16(float* c, const unsigned* a, const unsigned* b) {
    asm volatile("mma.sync.aligned.m16n8k16.row.col.f32.f16.f16.f32 "
                 "{%0,%1,%2,%3},{%4,%5,%6,%7},{%8,%9},{%0,%1,%2,%3};"
                 : "+f"(c[0]),"+f"(c[1]),"+f"(c[2]),"+f"(c[3])
                 : "r"(a[0]),"r"(a[1]),"r"(a[2]),"r"(a[3]),"r"(b[0]),"r"(b[1]));
}
__device__ __forceinline__ void cp16(unsigned dst, const void* src) {
    asm volatile("cp.async.cg.shared.global [%0], [%1], 16;" :: "r"(dst), "l"(src));
}
__device__ __forceinline__ void cp_commit() { asm volatile("cp.async.commit_group;"); }
template<int N> __device__ __forceinline__ void cp_wait() {
    asm volatile("cp.async.wait_group %0;" :: "n"(N));
}

// ---------------------------------------------------------------------------
// out[M,64] = gelu(X[M,K] @ W[K,64] (+ bias))
// 128 threads, 16-row tile, 2x4 micro-tile, K-chunks of 64, reg double-buffer.
// ---------------------------------------------------------------------------
__global__ __launch_bounds__(128) void lowrank_in_kernel(
    const float* __restrict__ X, const float* __restrict__ W,
    const float* __restrict__ bias, float* __restrict__ out, int K)
{
    __shared__ __align__(16) float Xs[16][68];
    __shared__ __align__(16) float Ws[64][68];
    const int tid = threadIdx.x;
    const int tx = tid & 15, ty = tid >> 4;
    const int m0 = blockIdx.x * 16;

    float4 xreg[2], wreg[8];
    #pragma unroll
    for (int ii = 0; ii < 2; ii++) {
        int idx = tid + 128 * ii, r = idx >> 4, c4 = (idx & 15) * 4;
        xreg[ii] = *(const float4*)&X[(m0 + r) * K + c4];
    }
    #pragma unroll
    for (int ii = 0; ii < 8; ii++) {
        int idx = tid + 128 * ii, r = idx >> 4, c4 = (idx & 15) * 4;
        wreg[ii] = *(const float4*)&W[r * 64 + c4];
    }
    float acc[2][4] = {};
    const int nk = K >> 6;
    for (int ch = 0; ch < nk; ch++) {
        #pragma unroll
        for (int ii = 0; ii < 2; ii++) {
            int idx = tid + 128 * ii, r = idx >> 4, c4 = (idx & 15) * 4;
            *(float4*)&Xs[r][c4] = xreg[ii];
        }
        #pragma unroll
        for (int ii = 0; ii < 8; ii++) {
            int idx = tid + 128 * ii, r = idx >> 4, c4 = (idx & 15) * 4;
            *(float4*)&Ws[r][c4] = wreg[ii];
        }
        __syncthreads();
        if (ch + 1 < nk) {
            int k0 = (ch + 1) << 6;
            #pragma unroll
            for (int ii = 0; ii < 2; ii++) {
                int idx = tid + 128 * ii, r = idx >> 4, c4 = (idx & 15) * 4;
                xreg[ii] = *(const float4*)&X[(m0 + r) * K + k0 + c4];
            }
            #pragma unroll
            for (int ii = 0; ii < 8; ii++) {
                int idx = tid + 128 * ii, r = idx >> 4, c4 = (idx & 15) * 4;
                wreg[ii] = *(const float4*)&W[(k0 + r) * 64 + c4];
            }
        }
        #pragma unroll
        for (int kk = 0; kk < 64; kk++) {
            float a0 = Xs[ty*2+0][kk];
            float a1 = Xs[ty*2+1][kk];
            float4 bv = *(const float4*)&Ws[kk][tx * 4];
            acc[0][0] += a0*bv.x; acc[0][1] += a0*bv.y; acc[0][2] += a0*bv.z; acc[0][3] += a0*bv.w;
            acc[1][0] += a1*bv.x; acc[1][1] += a1*bv.y; acc[1][2] += a1*bv.z; acc[1][3] += a1*bv.w;
        }
        __syncthreads();
    }
    #pragma unroll
    for (int i = 0; i < 2; i++) {
        float4 r;
        float* pr = (float*)&r;
        #pragma unroll
        for (int j = 0; j < 4; j++) {
            float v = acc[i][j];
            if (bias) v += bias[tx * 4 + j];
            pr[j] = gelu_exact(v);
        }
        *(float4*)&out[(m0 + ty*2 + i) * 64 + tx * 4] = r;
    }
}

// ---------------------------------------------------------------------------
// qkv = g_h[4096,64] @ w_qkv_b[64,3072] -> g_qh (x 0.125*log2e), g_kh, g_vTh.
// 64 rows x 128 cols per block, 256 threads, 4x8 micro-tile. Dynamic SMEM.
// ---------------------------------------------------------------------------
#define EXP_SMEM ((64*68 + 64*132) * 4)

__global__ __launch_bounds__(256) void expand_qkv_kernel(const float* __restrict__ Wb)
{
    extern __shared__ __align__(16) float esm[];
    float* Hs = esm;             // [64][68]
    float* Ws = esm + 64*68;     // [64][132]  (reused as transpose buffer, stride 129)
    const int tid = threadIdx.x;
    const int tx = tid & 15, ty = tid >> 4;      // 16 x 16 threads
    const int n0 = blockIdx.x * 128;
    const int m0 = blockIdx.y * 64;

    #pragma unroll
    for (int ii = 0; ii < 4; ii++) {             // Hs: 64x64 floats
        int idx = tid + 256*ii, r = idx >> 4, c4 = (idx & 15) * 4;
        *(float4*)&Hs[r*68 + c4] = *(const float4*)&g_h[(m0 + r)*64 + c4];
    }
    #pragma unroll
    for (int ii = 0; ii < 8; ii++) {             // Ws: 64x128 floats
        int idx = tid + 256*ii, r = idx >> 5, c4 = (idx & 31) * 4;
        *(float4*)&Ws[r*132 + c4] = *(const float4*)&Wb[r*(3*CDIM) + n0 + c4];
    }
    __syncthreads();

    float acc[4][8] = {};
    #pragma unroll
    for (int kk = 0; kk < 64; kk++) {
        float a[4];
        #pragma unroll
        for (int i = 0; i < 4; i++) a[i] = Hs[(ty*4 + i)*68 + kk];
        float4 b0 = *(const float4*)&Ws[kk*132 + tx*8];
        float4 b1 = *(const float4*)&Ws[kk*132 + tx*8 + 4];
        float bj[8] = {b0.x, b0.y, b0.z, b0.w, b1.x, b1.y, b1.z, b1.w};
        #pragma unroll
        for (int i = 0; i < 4; i++)
            #pragma unroll
            for (int j = 0; j < 8; j++) acc[i][j] += a[i]*bj[j];
    }

    const int comp = n0 >> 10;     // 0=q 1=k 2=v (uniform per block)
    const int bb   = m0 >> 11;
    const int ns0  = m0 & 2047;
    if (comp < 2) {
        const float sc = (comp == 0) ? (0.125f * 1.44269504088896341f) : 1.0f;
        __half* dst = (comp == 0) ? g_qh : g_kh;
        int c    = (n0 + tx*8) & 1023;
        int head = c >> 6, d = c & 63;
        #pragma unroll
        for (int i = 0; i < 4; i++) {
            int nseq = ns0 + ty*4 + i;
            size_t off = ((size_t)(bb*HEADS + head)*NSEQ + nseq)*DH + d;
            uint4 u;
            u.x = pack2(acc[i][0]*sc, acc[i][1]*sc);
            u.y = pack2(acc[i][2]*sc, acc[i][3]*sc);
            u.z = pack2(acc[i][4]*sc, acc[i][5]*sc);
            u.w = pack2(acc[i][6]*sc, acc[i][7]*sc);
            *(uint4*)&dst[off] = u;
        }
    } else {
        // stage [64 n][128 c] then write V^T fp16 coalesced
        float* Ts = Ws;   // stride 129 (needs 64*129 <= 64*132)
        __syncthreads();
        #pragma unroll
        for (int i = 0; i < 4; i++)
            #pragma unroll
            for (int j = 0; j < 8; j++)
                Ts[(ty*4 + i)*129 + tx*8 + j] = acc[i][j];
        __syncthreads();
        #pragma unroll
        for (int ii = 0; ii < 8; ii++) {
            int idx = tid + 256*ii;             // 2048 = 128 cols x 16 n-groups
            int c = idx >> 4, g4 = (idx & 15) * 4;
            int c10  = (n0 + c) & 1023;
            int head = c10 >> 6, d = c10 & 63;
            uint2 u;
            u.x = pack2(Ts[(g4+0)*129 + c], Ts[(g4+1)*129 + c]);
            u.y = pack2(Ts[(g4+2)*129 + c], Ts[(g4+3)*129 + c]);
            *(uint2*)&g_vTh[((size_t)(bb*HEADS + head)*DH + d)*NSEQ + ns0 + g4] = u;
        }
    }
}

// ---------------------------------------------------------------------------
// Flash attention, fp16 mma.m16n8k16, fp32 accum, exp2-domain softmax.
// Grid (NSEQ/128, B*H), 128 threads (4 warps), warp w owns q-rows [32w,32w+32).
// KV tile 64, 2-stage cp.async pipeline. P kept in registers (C-frag == A-frag).
// ---------------------------------------------------------------------------
#define LDH 72
#define FLASH_SMEM ((128 + 4*64) * LDH * 2)

__global__ __launch_bounds__(128) void flash_mma_kernel()
{
    extern __shared__ __align__(16) __half smh[];
    __half* Qs = smh;                                 // [128][LDH]

    const int tid  = threadIdx.x;
    const int lane = tid & 31, w = tid >> 5;
    const int bh = blockIdx.y;
    const int q0 = blockIdx.x * 128;
    const int b = bh >> 4, h = bh & 15;

    const __half* Qg  = g_qh  + ((size_t)bh * NSEQ + q0) * DH;
    const __half* Kg  = g_kh  + (size_t)bh * NSEQ * DH;
    const __half* VTg = g_vTh + (size_t)bh * DH * NSEQ;

    const unsigned sbase = (unsigned)__cvta_generic_to_shared(smh);
    // buffers (half offsets): Kb = 128*LDH + buf*128*LDH, Vb = Kb + 64*LDH

    // prologue: async-load tile 0 into buf 0
    {
        const __half* Kt = Kg;
        unsigned kdst = sbase + (unsigned)(128*LDH*2);
        unsigned vdst = kdst + (unsigned)(64*LDH*2);
        #pragma unroll
        for (int it = 0; it < 4; it++) {
            int i = tid + 128*it, r = i >> 3, c8 = (i & 7)*8;
            cp16(kdst + (unsigned)((r*LDH + c8)*2), &Kt[r*DH + c8]);
            cp16(vdst + (unsigned)((r*LDH + c8)*2), &VTg[(size_t)r*NSEQ + c8]);
        }
        cp_commit();
    }
    // Q tile (sync loads, overlapped with the async prologue)
    #pragma unroll
    for (int it = 0; it < 8; it++) {
        int i = tid + 128 * it, r = i >> 3, c8 = (i & 7) * 8;
        *(uint4*)&Qs[r*LDH + c8] = *(const uint4*)&Qg[r*DH + c8];
    }

    // ldmatrix per-lane byte offsets
    const unsigned aOff = (unsigned)((((lane & 15) * LDH) + (lane >> 4) * 8) * 2);
    const unsigned bOff = (unsigned)((((lane & 7) * LDH) + ((lane >> 3) & 1) * 8) * 2);
    const unsigned qsA = sbase + aOff;

    float o[2][8][4];
    float mrow[2][2], lrow[2][2];
    #pragma unroll
    for (int mt = 0; mt < 2; mt++) {
        mrow[mt][0] = mrow[mt][1] = -1e30f;
        lrow[mt][0] = lrow[mt][1] = 0.f;
        #pragma unroll
        for (int j = 0; j < 8; j++)
            o[mt][j][0] = o[mt][j][1] = o[mt][j][2] = o[mt][j][3] = 0.f;
    }

    for (int t = 0; t < NSEQ/64; t++) {
        if (t + 1 < NSEQ/64) {
            const __half* Kt = Kg + (size_t)(t+1) * 64 * DH;
            unsigned kdst = sbase + (unsigned)((128 + ((t+1)&1)*128)*LDH*2);
            unsigned vdst = kdst + (unsigned)(64*LDH*2);
            #pragma unroll
            for (int it = 0; it < 4; it++) {
                int i = tid + 128*it, r = i >> 3, c8 = (i & 7)*8;
                cp16(kdst + (unsigned)((r*LDH + c8)*2), &Kt[r*DH + c8]);
                cp16(vdst + (unsigned)((r*LDH + c8)*2), &VTg[(size_t)r*NSEQ + (t+1)*64 + c8]);
            }
            cp_commit();
            cp_wait<1>();
        } else {
            cp_wait<0>();
        }
        __syncthreads();

        const unsigned kB = sbase + (unsigned)((128 + (t&1)*128)*LDH*2) + bOff;
        const unsigned vB = kB + (unsigned)(64*LDH*2);

        // ---- S = Q K^T  (per warp: 2 m-tiles x 8 n-tiles, 4 k-steps) ----
        float s[2][8][4];
        #pragma unroll
        for (int mt = 0; mt < 2; mt++)
            #pragma unroll
            for (int j = 0; j < 8; j++)
                s[mt][j][0] = s[mt][j][1] = s[mt][j][2] = s[mt][j][3] = 0.f;

        #pragma unroll
        for (int ks = 0; ks < 4; ks++) {
            const int kk = ks * 16;
            unsigned bf[8][2];
            #pragma unroll
            for (int j = 0; j < 8; j++)
                ldsm2(bf[j][0], bf[j][1], kB + (unsigned)((j*8*LDH + kk) * 2));
            #pragma unroll
            for (int mt = 0; mt < 2; mt++) {
                unsigned af[4];
                ldsm4(af[0], af[1], af[2], af[3],
                      qsA + (unsigned)(((w*32 + mt*16)*LDH + kk) * 2));
                #pragma unroll
                for (int j = 0; j < 8; j++) mma16(s[mt][j], af, bf[j]);
            }
        }

        // ---- online softmax (log2 domain), P packed into registers ----
        unsigned pp[2][8][2];
        #pragma unroll
        for (int mt = 0; mt < 2; mt++) {
            float mxl = -1e30f, mxh = -1e30f;
            #pragma unroll
            for (int j = 0; j < 8; j++) {
                mxl = fmaxf(mxl, fmaxf(s[mt][j][0], s[mt][j][1]));
                mxh = fmaxf(mxh, fmaxf(s[mt][j][2], s[mt][j][3]));
            }
            mxl = fmaxf(mxl, __shfl_xor_sync(0xffffffffu, mxl, 1));
            mxl = fmaxf(mxl, __shfl_xor_sync(0xffffffffu, mxl, 2));
            mxh = fmaxf(mxh, __shfl_xor_sync(0xffffffffu, mxh, 1));
            mxh = fmaxf(mxh, __shfl_xor_sync(0xffffffffu, mxh, 2));
            float mln = fmaxf(mrow[mt][0], mxl);
            float mhn = fmaxf(mrow[mt][1], mxh);
            float al = exp2f(mrow[mt][0] - mln);
            float ah = exp2f(mrow[mt][1] - mhn);
            mrow[mt][0] = mln; mrow[mt][1] = mhn;
            float sl = 0.f, sh = 0.f;
            #pragma unroll
            for (int j = 0; j < 8; j++) {
                __half2 hl = __floats2half2_rn(exp2f(s[mt][j][0] - mln),
                                               exp2f(s[mt][j][1] - mln));
                __half2 hh = __floats2half2_rn(exp2f(s[mt][j][2] - mhn),
                                               exp2f(s[mt][j][3] - mhn));
                float2 fl = __half22float2(hl), fh = __half22float2(hh);
                sl += fl.x + fl.y; sh += fh.x + fh.y;
                pp[mt][j][0] = *(unsigned*)&hl;
                pp[mt][j][1] = *(unsigned*)&hh;
            }
            sl += __shfl_xor_sync(0xffffffffu, sl, 1);
            sl += __shfl_xor_sync(0xffffffffu, sl, 2);
            sh += __shfl_xor_sync(0xffffffffu, sh, 1);
            sh += __shfl_xor_sync(0xffffffffu, sh, 2);
            lrow[mt][0] = lrow[mt][0]*al + sl;
            lrow[mt][1] = lrow[mt][1]*ah + sh;
            #pragma unroll
            for (int j = 0; j < 8; j++) {
                o[mt][j][0] *= al; o[mt][j][1] *= al;
                o[mt][j][2] *= ah; o[mt][j][3] *= ah;
            }
        }

        // ---- O += P V  (A straight from S accumulators; B from V^T SMEM) ----
        #pragma unroll
        for (int ks = 0; ks < 4; ks++) {
            const int kc = ks * 16;
            unsigned bf[8][2];
            #pragma unroll
            for (int jd = 0; jd < 8; jd++)
                ldsm2(bf[jd][0], bf[jd][1], vB + (unsigned)((jd*8*LDH + kc) * 2));
            #pragma unroll
            for (int mt = 0; mt < 2; mt++) {
                unsigned af[4] = { pp[mt][2*ks][0], pp[mt][2*ks][1],
                                   pp[mt][2*ks+1][0], pp[mt][2*ks+1][1] };
                #pragma unroll
                for (int jd = 0; jd < 8; jd++) mma16(o[mt][jd], af, bf[jd]);
            }
        }
        __syncthreads();   // everyone done reading this buffer before it refills
    }

    // ---- epilogue (fp32 out to [B,N,C]) ----
    #pragma unroll
    for (int mt = 0; mt < 2; mt++) {
        float il = 1.0f / lrow[mt][0], ih = 1.0f / lrow[mt][1];
        int rowl = q0 + w*32 + mt*16 + (lane >> 2);
        size_t basel = ((size_t)(b*NSEQ + rowl))*CDIM + h*DH + (lane & 3)*2;
        size_t baseh = basel + (size_t)8*CDIM;
        #pragma unroll
        for (int j = 0; j < 8; j++) {
            *(float2*)&g_attn[basel + j*8] = make_float2(o[mt][j][0]*il, o[mt][j][1]*il);
            *(float2*)&g_attn[baseh + j*8] = make_float2(o[mt][j][2]*ih, o[mt][j][3]*ih);
        }
    }
}

// ---------------------------------------------------------------------------
// y[M,1024] = g_h2[M,64] @ w_proj_b[64,1024] + b_proj_b
// ---------------------------------------------------------------------------
__global__ __launch_bounds__(256) void lowrank_out_kernel(
    const float* __restrict__ Wb, const float* __restrict__ bias,
    float* __restrict__ out)
{
    __shared__ __align__(16) float Hs[32][68];
    __shared__ __align__(16) float Ws[64][132];
    const int tid = threadIdx.x;
    const int tx = tid & 15, ty = tid >> 4;
    const int n0 = blockIdx.x * 128;
    const int m0 = blockIdx.y * 32;
    for (int i = tid; i < 32*64; i += 256) {
        int r = i >> 6, k = i & 63;
        Hs[r][k] = g_h2[(m0 + r) * 64 + k];
    }
    for (int i = tid; i < 64*128; i += 256) {
        int k = i >> 7, c = i & 127;
        Ws[k][c] = Wb[k * CDIM + n0 + c];
    }
    __syncthreads();
    float acc[2][8] = {};
    #pragma unroll
    for (int kk = 0; kk < 64; kk++) {
        float a0 = Hs[ty*2+0][kk];
        float a1 = Hs[ty*2+1][kk];
        float4 b0 = *(const float4*)&Ws[kk][tx*8];
        float4 b1 = *(const float4*)&Ws[kk][tx*8+4];
        float bj[8] = {b0.x, b0.y, b0.z, b0.w, b1.x, b1.y, b1.z, b1.w};
        #pragma unroll
        for (int j = 0; j < 8; j++) { acc[0][j] += a0*bj[j]; acc[1][j] += a1*bj[j]; }
    }
    float4 bv0 = *(const float4*)&bias[n0 + tx*8];
    float4 bv1 = *(const float4*)&bias[n0 + tx*8 + 4];
    #pragma unroll
    for (int i = 0; i < 2; i++) {
        size_t base = (size_t)(m0 + ty*2 + i)*CDIM + n0 + tx*8;
        *(float4*)&out[base]     = make_float4(acc[i][0]+bv0.x, acc[i][1]+bv0.y, acc[i][2]+bv0.z, acc[i][3]+bv0.w);
        *(float4*)&out[base + 4] = make_float4(acc[i][4]+bv1.x, acc[i][5]+bv1.y, acc[i][6]+bv1.z, acc[i][7]+bv1.w);
    }
}

// ---------------------------------------------------------------------------
extern "C" void kernel_launch(void* const* d_in, const int* in_sizes, int n_in,
                              void* d_out, int out_size)
{
    const float* x        = (const float*)d_in[0];
    const float* w_qkv_a  = (const float*)d_in[1];
    const float* w_qkv_b  = (const float*)d_in[2];
    const float* w_proj_a = (const float*)d_in[3];
    const float* b_proj_a = (const float*)d_in[4];
    const float* w_proj_b = (const float*)d_in[5];
    const float* b_proj_b = (const float*)d_in[6];
    float* out = (float*)d_out;

    float *ph = nullptr, *ph2 = nullptr, *pattn = nullptr;
    cudaGetSymbolAddress((void**)&ph,    g_h);
    cudaGetSymbolAddress((void**)&ph2,   g_h2);
    cudaGetSymbolAddress((void**)&pattn, g_attn);

    static bool attr_set = false;
    if (!attr_set) {
        cudaFuncSetAttribute(flash_mma_kernel,
                             cudaFuncAttributeMaxDynamicSharedMemorySize, FLASH_SMEM);
        cudaFuncSetAttribute(expand_qkv_kernel,
                             cudaFuncAttributeMaxDynamicSharedMemorySize, EXP_SMEM);
        attr_set = true;
    }

    // 1. h = gelu(x @ w_qkv_a)                    [4096,64]
    lowrank_in_kernel<<<MTOT/16, 128>>>(x, w_qkv_a, nullptr, ph, CDIM);
    // 2. qkv = h @ w_qkv_b -> q (x0.125*log2e), k, vT  (all fp16)
    expand_qkv_kernel<<<dim3(3*CDIM/128, MTOT/64), 256, EXP_SMEM>>>(w_qkv_b);
    // 3. fp16 tensor-core flash attention -> g_attn [B,N,C]
    flash_mma_kernel<<<dim3(NSEQ/128, BD*HEADS), 128, FLASH_SMEM>>>();
    // 4. h2 = gelu(attn @ w_proj_a + b_proj_a)    [4096,64]
    lowrank_in_kernel<<<MTOT/16, 128>>>(pattn, w_proj_a, b_proj_a, ph2, CDIM);
    // 5. y = h2 @ w_proj_b + b_proj_b             [4096,1024]
    lowrank_out_kernel<<<dim3(CDIM/128, MTOT/32), 256>>>(w_proj_b, b_proj_b, out);
}

// round 7
// speedup vs baseline: 6.0024x; 1.3412x over previous
#include <cuda_runtime.h>
#include <cuda_fp16.h>
#include <math.h>

#define BD    2
#define NSEQ  2048
#define CDIM  1024
#define RANK  64
#define HEADS 16
#define DH    64
#define MTOT  (BD*NSEQ)   // 4096

// Scratch (device globals: no allocation allowed in kernel_launch)
__device__ __half g_hh  [MTOT*RANK];            // gelu(x @ w_qkv_a), fp16
__device__ __half g_h2h [MTOT*RANK];            // gelu(attn @ w_proj_a + b), fp16
__device__ __half g_qh  [BD*HEADS*NSEQ*DH];     // Q * 0.125*log2e, fp16 [bh][n][d]
__device__ __half g_kh  [BD*HEADS*NSEQ*DH];     // K fp16               [bh][n][d]
__device__ __half g_vTh [BD*HEADS*DH*NSEQ];     // V^T fp16             [bh][d][n]
__device__ float  g_attn[MTOT*CDIM];            // attention out [B,N,C]

__device__ __forceinline__ float gelu_exact(float v) {
    return 0.5f * v * (1.0f + erff(v * 0.70710678118654752440f));
}
__device__ __forceinline__ unsigned pack2(float a, float b) {
    __half2 h = __floats2half2_rn(a, b);
    return *(unsigned*)&h;
}
__device__ __forceinline__ void ldsm4(unsigned &r0, unsigned &r1, unsigned &r2, unsigned &r3, unsigned a) {
    asm volatile("ldmatrix.sync.aligned.m8n8.x4.shared.b16 {%0,%1,%2,%3}, [%4];"
                 : "=r"(r0),"=r"(r1),"=r"(r2),"=r"(r3) : "r"(a));
}
__device__ __forceinline__ void ldsm2(unsigned &r0, unsigned &r1, unsigned a) {
    asm volatile("ldmatrix.sync.aligned.m8n8.x2.shared.b16 {%0,%1}, [%2];"
                 : "=r"(r0),"=r"(r1) : "r"(a));
}
__device__ __forceinline__ void ldsm2t(unsigned &r0, unsigned &r1, unsigned a) {
    asm volatile("ldmatrix.sync.aligned.m8n8.x2.trans.shared.b16 {%0,%1}, [%2];"
                 : "=r"(r0),"=r"(r1) : "r"(a));
}
__device__ __forceinline__ void mma16(float* c, const unsigned* a, const unsigned* b) {
    asm volatile("mma.sync.aligned.m16n8k16.row.col.f32.f16.f16.f32 "
                 "{%0,%1,%2,%3},{%4,%5,%6,%7},{%8,%9},{%0,%1,%2,%3};"
                 : "+f"(c[0]),"+f"(c[1]),"+f"(c[2]),"+f"(c[3])
                 : "r"(a[0]),"r"(a[1]),"r"(a[2]),"r"(a[3]),"r"(b[0]),"r"(b[1]));
}
__device__ __forceinline__ void cp16(unsigned dst, const void* src) {
    asm volatile("cp.async.cg.shared.global [%0], [%1], 16;" :: "r"(dst), "l"(src));
}
__device__ __forceinline__ void cp_commit() { asm volatile("cp.async.commit_group;"); }
template<int N> __device__ __forceinline__ void cp_wait() {
    asm volatile("cp.async.wait_group %0;" :: "n"(N));
}

// ---------------------------------------------------------------------------
// out_fp16[M,64] = gelu(X[M,K] @ W[K,64] (+ bias))   (K=1024, fp32 SIMT math)
// 128 threads, 16-row tile, 2x4 micro-tile, K-chunks of 64, reg double-buffer.
// ---------------------------------------------------------------------------
__global__ __launch_bounds__(128) void lowrank_in_kernel(
    const float* __restrict__ X, const float* __restrict__ W,
    const float* __restrict__ bias, __half* __restrict__ out, int K)
{
    __shared__ __align__(16) float Xs[16][68];
    __shared__ __align__(16) float Ws[64][68];
    const int tid = threadIdx.x;
    const int tx = tid & 15, ty = tid >> 4;
    const int m0 = blockIdx.x * 16;

    float4 xreg[2], wreg[8];
    #pragma unroll
    for (int ii = 0; ii < 2; ii++) {
        int idx = tid + 128 * ii, r = idx >> 4, c4 = (idx & 15) * 4;
        xreg[ii] = *(const float4*)&X[(m0 + r) * K + c4];
    }
    #pragma unroll
    for (int ii = 0; ii < 8; ii++) {
        int idx = tid + 128 * ii, r = idx >> 4, c4 = (idx & 15) * 4;
        wreg[ii] = *(const float4*)&W[r * 64 + c4];
    }
    float acc[2][4] = {};
    const int nk = K >> 6;
    for (int ch = 0; ch < nk; ch++) {
        #pragma unroll
        for (int ii = 0; ii < 2; ii++) {
            int idx = tid + 128 * ii, r = idx >> 4, c4 = (idx & 15) * 4;
            *(float4*)&Xs[r][c4] = xreg[ii];
        }
        #pragma unroll
        for (int ii = 0; ii < 8; ii++) {
            int idx = tid + 128 * ii, r = idx >> 4, c4 = (idx & 15) * 4;
            *(float4*)&Ws[r][c4] = wreg[ii];
        }
        __syncthreads();
        if (ch + 1 < nk) {
            int k0 = (ch + 1) << 6;
            #pragma unroll
            for (int ii = 0; ii < 2; ii++) {
                int idx = tid + 128 * ii, r = idx >> 4, c4 = (idx & 15) * 4;
                xreg[ii] = *(const float4*)&X[(m0 + r) * K + k0 + c4];
            }
            #pragma unroll
            for (int ii = 0; ii < 8; ii++) {
                int idx = tid + 128 * ii, r = idx >> 4, c4 = (idx & 15) * 4;
                wreg[ii] = *(const float4*)&W[(k0 + r) * 64 + c4];
            }
        }
        #pragma unroll
        for (int kk = 0; kk < 64; kk++) {
            float a0 = Xs[ty*2+0][kk];
            float a1 = Xs[ty*2+1][kk];
            float4 bv = *(const float4*)&Ws[kk][tx * 4];
            acc[0][0] += a0*bv.x; acc[0][1] += a0*bv.y; acc[0][2] += a0*bv.z; acc[0][3] += a0*bv.w;
            acc[1][0] += a1*bv.x; acc[1][1] += a1*bv.y; acc[1][2] += a1*bv.z; acc[1][3] += a1*bv.w;
        }
        __syncthreads();
    }
    #pragma unroll
    for (int i = 0; i < 2; i++) {
        float pr[4];
        #pragma unroll
        for (int j = 0; j < 4; j++) {
            float v = acc[i][j];
            if (bias) v += bias[tx * 4 + j];
            pr[j] = gelu_exact(v);
        }
        uint2 u;
        u.x = pack2(pr[0], pr[1]);
        u.y = pack2(pr[2], pr[3]);
        *(uint2*)&out[(m0 + ty*2 + i) * 64 + tx * 4] = u;
    }
}

// ---------------------------------------------------------------------------
// qkv = g_hh[4096,64] @ w_qkv_b[64,3072] via fp16 mma ->
//   g_qh (x 0.125*log2e), g_kh, g_vTh (transposed via SMEM staging).
// Tile 64m x 128n, K=64 (4 mma k-steps). 128 threads (4 warps, 16 rows each).
// B fragments via ldmatrix.trans on row-major [k][n] fp16 weight tile.
// ---------------------------------------------------------------------------
__global__ __launch_bounds__(128) void expand_mma_kernel(const float* __restrict__ Wb)
{
    __shared__ __align__(16) __half Hs[64*72];      // A: rows m, cols k
    __shared__ __align__(16) __half Wsm[64*136];    // B: rows k, cols n (128+8 pad)
    const int tid = threadIdx.x, lane = tid & 31, w = tid >> 5;
    const int n0 = blockIdx.x * 128;
    const int m0 = blockIdx.y * 64;

    #pragma unroll
    for (int ii = 0; ii < 4; ii++) {                 // h tile 64x64 fp16
        int idx = tid + 128*ii, r = idx >> 3, c8 = (idx & 7) * 8;
        *(uint4*)&Hs[r*72 + c8] = *(const uint4*)&g_hh[(m0 + r)*64 + c8];
    }
    #pragma unroll
    for (int ii = 0; ii < 16; ii++) {                // Wb tile 64x128 fp32 -> fp16
        int idx = tid + 128*ii, r = idx >> 5, c4 = (idx & 31) * 4;
        float4 v = *(const float4*)&Wb[r*(3*CDIM) + n0 + c4];
        uint2 u; u.x = pack2(v.x, v.y); u.y = pack2(v.z, v.w);
        *(uint2*)&Wsm[r*136 + c4] = u;
    }
    __syncthreads();

    const unsigned hA = (unsigned)__cvta_generic_to_shared(Hs)
                      + (unsigned)(((w*16 + (lane & 15))*72 + (lane >> 4)*8) * 2);
    const unsigned wB = (unsigned)__cvta_generic_to_shared(Wsm)
                      + (unsigned)(((lane & 15)*136) * 2);

    float acc[16][4] = {};
    #pragma unroll
    for (int ks = 0; ks < 4; ks++) {
        const int kk = ks * 16;
        unsigned af[4];
        ldsm4(af[0], af[1], af[2], af[3], hA + (unsigned)(kk * 2));
        #pragma unroll
        for (int j = 0; j < 16; j++) {
            unsigned bf[2];
            ldsm2t(bf[0], bf[1], wB + (unsigned)((kk*136 + j*8) * 2));
            mma16(acc[j], af, bf);
        }
    }

    const int comp = n0 >> 10;     // 0=q 1=k 2=v (uniform per block)
    const int bb   = m0 >> 11;
    const int ns0  = m0 & 2047;
    const int rA   = w*16 + (lane >> 2);

    if (comp < 2) {
        const float sc = (comp == 0) ? (0.125f * 1.44269504088896341f) : 1.0f;
        __half* dst = (comp == 0) ? g_qh : g_kh;
        #pragma unroll
        for (int j = 0; j < 16; j++) {
            int gn   = (n0 + j*8 + (lane & 3)*2) & 1023;
            int head = gn >> 6, d = gn & 63;
            size_t base = ((size_t)(bb*HEADS + head)*NSEQ + ns0);
            *(unsigned*)&dst[(base + rA    )*DH + d] = pack2(acc[j][0]*sc, acc[j][1]*sc);
            *(unsigned*)&dst[(base + rA + 8)*DH + d] = pack2(acc[j][2]*sc, acc[j][3]*sc);
        }
    } else {
        // stage transposed [c=128][n=64] halves (stride 72), then coalesced V^T writes
        __syncthreads();                      // all ldsm reads done; reuse SMEM
        __half* Ts = Hs;                      // 128*72 halves = 18.4 KB <= 26.6 KB
        #pragma unroll
        for (int j = 0; j < 16; j++) {
            int c = j*8 + (lane & 3)*2;
            Ts[(c+0)*72 + rA    ] = __float2half(acc[j][0]);
            Ts[(c+1)*72 + rA    ] = __float2half(acc[j][1]);
            Ts[(c+0)*72 + rA + 8] = __float2half(acc[j][2]);
            Ts[(c+1)*72 + rA + 8] = __float2half(acc[j][3]);
        }
        __syncthreads();
        int c    = tid;                       // 128 cols <-> 128 threads
        int gn   = (n0 + c) & 1023;
        int head = gn >> 6, d = gn & 63;
        size_t base = ((size_t)(bb*HEADS + head)*DH + d)*NSEQ + ns0;
        #pragma unroll
        for (int g = 0; g < 8; g++)
            *(uint4*)&g_vTh[base + g*8] = *(uint4*)&Ts[c*72 + g*8];
    }
}

// ---------------------------------------------------------------------------
// y[4096,1024] = g_h2h[4096,64] @ w_proj_b[64,1024] + b_proj_b   (fp16 mma)
// Tile 64m x 128n, K=64. fp32 output straight to d_out.
// ---------------------------------------------------------------------------
__global__ __launch_bounds__(128) void lowrank_out_mma_kernel(
    const float* __restrict__ Wb, const float* __restrict__ bias,
    float* __restrict__ out)
{
    __shared__ __align__(16) __half Hs[64*72];
    __shared__ __align__(16) __half Wsm[64*136];
    const int tid = threadIdx.x, lane = tid & 31, w = tid >> 5;
    const int n0 = blockIdx.x * 128;
    const int m0 = blockIdx.y * 64;

    #pragma unroll
    for (int ii = 0; ii < 4; ii++) {
        int idx = tid + 128*ii, r = idx >> 3, c8 = (idx & 7) * 8;
        *(uint4*)&Hs[r*72 + c8] = *(const uint4*)&g_h2h[(m0 + r)*64 + c8];
    }
    #pragma unroll
    for (int ii = 0; ii < 16; ii++) {
        int idx = tid + 128*ii, r = idx >> 5, c4 = (idx & 31) * 4;
        float4 v = *(const float4*)&Wb[r*CDIM + n0 + c4];
        uint2 u; u.x = pack2(v.x, v.y); u.y = pack2(v.z, v.w);
        *(uint2*)&Wsm[r*136 + c4] = u;
    }
    __syncthreads();

    const unsigned hA = (unsigned)__cvta_generic_to_shared(Hs)
                      + (unsigned)(((w*16 + (lane & 15))*72 + (lane >> 4)*8) * 2);
    const unsigned wB = (unsigned)__cvta_generic_to_shared(Wsm)
                      + (unsigned)(((lane & 15)*136) * 2);

    float acc[16][4] = {};
    #pragma unroll
    for (int ks = 0; ks < 4; ks++) {
        const int kk = ks * 16;
        unsigned af[4];
        ldsm4(af[0], af[1], af[2], af[3], hA + (unsigned)(kk * 2));
        #pragma unroll
        for (int j = 0; j < 16; j++) {
            unsigned bf[2];
            ldsm2t(bf[0], bf[1], wB + (unsigned)((kk*136 + j*8) * 2));
            mma16(acc[j], af, bf);
        }
    }

    const int rA = w*16 + (lane >> 2);
    #pragma unroll
    for (int j = 0; j < 16; j++) {
        int n = n0 + j*8 + (lane & 3)*2;
        float2 bv = *(const float2*)&bias[n];
        size_t b0 = (size_t)(m0 + rA    )*CDIM + n;
        size_t b1 = (size_t)(m0 + rA + 8)*CDIM + n;
        *(float2*)&out[b0] = make_float2(acc[j][0] + bv.x, acc[j][1] + bv.y);
        *(float2*)&out[b1] = make_float2(acc[j][2] + bv.x, acc[j][3] + bv.y);
    }
}

// ---------------------------------------------------------------------------
// Flash attention, fp16 mma.m16n8k16, fp32 accum, exp2-domain softmax.
// Grid (NSEQ/128, B*H), 128 threads (4 warps), warp w owns q-rows [32w,32w+32).
// KV tile 64, 2-stage cp.async pipeline. P kept in registers (C-frag == A-frag).
// ---------------------------------------------------------------------------
#define LDH 72
#define FLASH_SMEM ((128 + 4*64) * LDH * 2)

__global__ __launch_bounds__(128) void flash_mma_kernel()
{
    extern __shared__ __align__(16) __half smh[];
    __half* Qs = smh;                                 // [128][LDH]

    const int tid  = threadIdx.x;
    const int lane = tid & 31, w = tid >> 5;
    const int bh = blockIdx.y;
    const int q0 = blockIdx.x * 128;
    const int b = bh >> 4, h = bh & 15;

    const __half* Qg  = g_qh  + ((size_t)bh * NSEQ + q0) * DH;
    const __half* Kg  = g_kh  + (size_t)bh * NSEQ * DH;
    const __half* VTg = g_vTh + (size_t)bh * DH * NSEQ;

    const unsigned sbase = (unsigned)__cvta_generic_to_shared(smh);

    // prologue: async-load tile 0 into buf 0
    {
        unsigned kdst = sbase + (unsigned)(128*LDH*2);
        unsigned vdst = kdst + (unsigned)(64*LDH*2);
        #pragma unroll
        for (int it = 0; it < 4; it++) {
            int i = tid + 128*it, r = i >> 3, c8 = (i & 7)*8;
            cp16(kdst + (unsigned)((r*LDH + c8)*2), &Kg[r*DH + c8]);
            cp16(vdst + (unsigned)((r*LDH + c8)*2), &VTg[(size_t)r*NSEQ + c8]);
        }
        cp_commit();
    }
    #pragma unroll
    for (int it = 0; it < 8; it++) {
        int i = tid + 128 * it, r = i >> 3, c8 = (i & 7) * 8;
        *(uint4*)&Qs[r*LDH + c8] = *(const uint4*)&Qg[r*DH + c8];
    }

    const unsigned aOff = (unsigned)((((lane & 15) * LDH) + (lane >> 4) * 8) * 2);
    const unsigned bOff = (unsigned)((((lane & 7) * LDH) + ((lane >> 3) & 1) * 8) * 2);
    const unsigned qsA = sbase + aOff;

    float o[2][8][4];
    float mrow[2][2], lrow[2][2];
    #pragma unroll
    for (int mt = 0; mt < 2; mt++) {
        mrow[mt][0] = mrow[mt][1] = -1e30f;
        lrow[mt][0] = lrow[mt][1] = 0.f;
        #pragma unroll
        for (int j = 0; j < 8; j++)
            o[mt][j][0] = o[mt][j][1] = o[mt][j][2] = o[mt][j][3] = 0.f;
    }

    for (int t = 0; t < NSEQ/64; t++) {
        if (t + 1 < NSEQ/64) {
            const __half* Kt = Kg + (size_t)(t+1) * 64 * DH;
            unsigned kdst = sbase + (unsigned)((128 + ((t+1)&1)*128)*LDH*2);
            unsigned vdst = kdst + (unsigned)(64*LDH*2);
            #pragma unroll
            for (int it = 0; it < 4; it++) {
                int i = tid + 128*it, r = i >> 3, c8 = (i & 7)*8;
                cp16(kdst + (unsigned)((r*LDH + c8)*2), &Kt[r*DH + c8]);
                cp16(vdst + (unsigned)((r*LDH + c8)*2), &VTg[(size_t)r*NSEQ + (t+1)*64 + c8]);
            }
            cp_commit();
            cp_wait<1>();
        } else {
            cp_wait<0>();
        }
        __syncthreads();

        const unsigned kB = sbase + (unsigned)((128 + (t&1)*128)*LDH*2) + bOff;
        const unsigned vB = kB + (unsigned)(64*LDH*2);

        // ---- S = Q K^T ----
        float s[2][8][4];
        #pragma unroll
        for (int mt = 0; mt < 2; mt++)
            #pragma unroll
            for (int j = 0; j < 8; j++)
                s[mt][j][0] = s[mt][j][1] = s[mt][j][2] = s[mt][j][3] = 0.f;

        #pragma unroll
        for (int ks = 0; ks < 4; ks++) {
            const int kk = ks * 16;
            unsigned bf[8][2];
            #pragma unroll
            for (int j = 0; j < 8; j++)
                ldsm2(bf[j][0], bf[j][1], kB + (unsigned)((j*8*LDH + kk) * 2));
            #pragma unroll
            for (int mt = 0; mt < 2; mt++) {
                unsigned af[4];
                ldsm4(af[0], af[1], af[2], af[3],
                      qsA + (unsigned)(((w*32 + mt*16)*LDH + kk) * 2));
                #pragma unroll
                for (int j = 0; j < 8; j++) mma16(s[mt][j], af, bf[j]);
            }
        }

        // ---- online softmax (log2 domain), P packed into registers ----
        unsigned pp[2][8][2];
        #pragma unroll
        for (int mt = 0; mt < 2; mt++) {
            float mxl = -1e30f, mxh = -1e30f;
            #pragma unroll
            for (int j = 0; j < 8; j++) {
                mxl = fmaxf(mxl, fmaxf(s[mt][j][0], s[mt][j][1]));
                mxh = fmaxf(mxh, fmaxf(s[mt][j][2], s[mt][j][3]));
            }
            mxl = fmaxf(mxl, __shfl_xor_sync(0xffffffffu, mxl, 1));
            mxl = fmaxf(mxl, __shfl_xor_sync(0xffffffffu, mxl, 2));
            mxh = fmaxf(mxh, __shfl_xor_sync(0xffffffffu, mxh, 1));
            mxh = fmaxf(mxh, __shfl_xor_sync(0xffffffffu, mxh, 2));
            float mln = fmaxf(mrow[mt][0], mxl);
            float mhn = fmaxf(mrow[mt][1], mxh);
            float al = exp2f(mrow[mt][0] - mln);
            float ah = exp2f(mrow[mt][1] - mhn);
            mrow[mt][0] = mln; mrow[mt][1] = mhn;
            float sl = 0.f, sh = 0.f;
            #pragma unroll
            for (int j = 0; j < 8; j++) {
                __half2 hl = __floats2half2_rn(exp2f(s[mt][j][0] - mln),
                                               exp2f(s[mt][j][1] - mln));
                __half2 hh = __floats2half2_rn(exp2f(s[mt][j][2] - mhn),
                                               exp2f(s[mt][j][3] - mhn));
                float2 fl = __half22float2(hl), fh = __half22float2(hh);
                sl += fl.x + fl.y; sh += fh.x + fh.y;
                pp[mt][j][0] = *(unsigned*)&hl;
                pp[mt][j][1] = *(unsigned*)&hh;
            }
            sl += __shfl_xor_sync(0xffffffffu, sl, 1);
            sl += __shfl_xor_sync(0xffffffffu, sl, 2);
            sh += __shfl_xor_sync(0xffffffffu, sh, 1);
            sh += __shfl_xor_sync(0xffffffffu, sh, 2);
            lrow[mt][0] = lrow[mt][0]*al + sl;
            lrow[mt][1] = lrow[mt][1]*ah + sh;
            #pragma unroll
            for (int j = 0; j < 8; j++) {
                o[mt][j][0] *= al; o[mt][j][1] *= al;
                o[mt][j][2] *= ah; o[mt][j][3] *= ah;
            }
        }

        // ---- O += P V ----
        #pragma unroll
        for (int ks = 0; ks < 4; ks++) {
            const int kc = ks * 16;
            unsigned bf[8][2];
            #pragma unroll
            for (int jd = 0; jd < 8; jd++)
                ldsm2(bf[jd][0], bf[jd][1], vB + (unsigned)((jd*8*LDH + kc) * 2));
            #pragma unroll
            for (int mt = 0; mt < 2; mt++) {
                unsigned af[4] = { pp[mt][2*ks][0], pp[mt][2*ks][1],
                                   pp[mt][2*ks+1][0], pp[mt][2*ks+1][1] };
                #pragma unroll
                for (int jd = 0; jd < 8; jd++) mma16(o[mt][jd], af, bf[jd]);
            }
        }
        __syncthreads();
    }

    // ---- epilogue ----
    #pragma unroll
    for (int mt = 0; mt < 2; mt++) {
        float il = 1.0f / lrow[mt][0], ih = 1.0f / lrow[mt][1];
        int rowl = q0 + w*32 + mt*16 + (lane >> 2);
        size_t basel = ((size_t)(b*NSEQ + rowl))*CDIM + h*DH + (lane & 3)*2;
        size_t baseh = basel + (size_t)8*CDIM;
        #pragma unroll
        for (int j = 0; j < 8; j++) {
            *(float2*)&g_attn[basel + j*8] = make_float2(o[mt][j][0]*il, o[mt][j][1]*il);
            *(float2*)&g_attn[baseh + j*8] = make_float2(o[mt][j][2]*ih, o[mt][j][3]*ih);
        }
    }
}

// ---------------------------------------------------------------------------
extern "C" void kernel_launch(void* const* d_in, const int* in_sizes, int n_in,
                              void* d_out, int out_size)
{
    const float* x        = (const float*)d_in[0];
    const float* w_qkv_a  = (const float*)d_in[1];
    const float* w_qkv_b  = (const float*)d_in[2];
    const float* w_proj_a = (const float*)d_in[3];
    const float* b_proj_a = (const float*)d_in[4];
    const float* w_proj_b = (const float*)d_in[5];
    const float* b_proj_b = (const float*)d_in[6];
    float* out = (float*)d_out;

    __half *phh = nullptr, *ph2h = nullptr;
    float  *pattn = nullptr;
    cudaGetSymbolAddress((void**)&phh,   g_hh);
    cudaGetSymbolAddress((void**)&ph2h,  g_h2h);
    cudaGetSymbolAddress((void**)&pattn, g_attn);

    static bool attr_set = false;
    if (!attr_set) {
        cudaFuncSetAttribute(flash_mma_kernel,
                             cudaFuncAttributeMaxDynamicSharedMemorySize, FLASH_SMEM);
        attr_set = true;
    }

    // 1. h = gelu(x @ w_qkv_a)                 fp16 [4096,64]
    lowrank_in_kernel<<<MTOT/16, 128>>>(x, w_qkv_a, nullptr, phh, CDIM);
    // 2. qkv = h @ w_qkv_b (mma) -> q (x0.125*log2e), k, vT  (fp16)
    expand_mma_kernel<<<dim3(3*CDIM/128, MTOT/64), 128>>>(w_qkv_b);
    // 3. fp16 tensor-core flash attention -> g_attn [B,N,C] fp32
    flash_mma_kernel<<<dim3(NSEQ/128, BD*HEADS), 128, FLASH_SMEM>>>();
    // 4. h2 = gelu(attn @ w_proj_a + b_proj_a) fp16 [4096,64]
    lowrank_in_kernel<<<MTOT/16, 128>>>(pattn, w_proj_a, b_proj_a, ph2h, CDIM);
    // 5. y = h2 @ w_proj_b + b_proj_b (mma)    fp32 [4096,1024]
    lowrank_out_mma_kernel<<<dim3(CDIM/128, MTOT/64), 128>>>(w_proj_b, b_proj_b, out);
}

// round 9
// speedup vs baseline: 7.2720x; 1.2115x over previous
#include <cuda_runtime.h>
#include <cuda_fp16.h>
#include <math.h>

#define BD    2
#define NSEQ  2048
#define CDIM  1024
#define RANK  64
#define HEADS 16
#define DH    64
#define MTOT  (BD*NSEQ)   // 4096
#define KDIM  1024

// Scratch (device globals: no allocation allowed in kernel_launch)
__device__ __half g_wah [2*KDIM*RANK];          // fp16 w_qkv_a | w_proj_a
__device__ __half g_hh  [MTOT*RANK];            // gelu(x @ w_qkv_a), fp16
__device__ __half g_h2h [MTOT*RANK];            // gelu(attn @ w_proj_a + b), fp16
__device__ __half g_qh  [BD*HEADS*NSEQ*DH];     // Q * 0.125*log2e, fp16 [bh][n][d]
__device__ __half g_kh  [BD*HEADS*NSEQ*DH];     // K fp16               [bh][n][d]
__device__ __half g_vTh [BD*HEADS*DH*NSEQ];     // V^T fp16             [bh][d][n]
__device__ __half g_attnh[MTOT*CDIM];           // attention out [B,N,C] fp16

__device__ __forceinline__ float gelu_exact(float v) {
    return 0.5f * v * (1.0f + erff(v * 0.70710678118654752440f));
}
__device__ __forceinline__ unsigned pack2(float a, float b) {
    __half2 h = __floats2half2_rn(a, b);
    return *(unsigned*)&h;
}
__device__ __forceinline__ void ldsm4(unsigned &r0, unsigned &r1, unsigned &r2, unsigned &r3, unsigned a) {
    asm volatile("ldmatrix.sync.aligned.m8n8.x4.shared.b16 {%0,%1,%2,%3}, [%4];"
                 : "=r"(r0),"=r"(r1),"=r"(r2),"=r"(r3) : "r"(a));
}
__device__ __forceinline__ void ldsm2(unsigned &r0, unsigned &r1, unsigned a) {
    asm volatile("ldmatrix.sync.aligned.m8n8.x2.shared.b16 {%0,%1}, [%2];"
                 : "=r"(r0),"=r"(r1) : "r"(a));
}
__device__ __forceinline__ void ldsm2t(unsigned &r0, unsigned &r1, unsigned a) {
    asm volatile("ldmatrix.sync.aligned.m8n8.x2.trans.shared.b16 {%0,%1}, [%2];"
                 : "=r"(r0),"=r"(r1) : "r"(a));
}
__device__ __forceinline__ void mma16(float* c, const unsigned* a, const unsigned* b) {
    asm volatile("mma.sync.aligned.m16n8k16.row.col.f32.f16.f16.f32 "
                 "{%0,%1,%2,%3},{%4,%5,%6,%7},{%8,%9},{%0,%1,%2,%3};"
                 : "+f"(c[0]),"+f"(c[1]),"+f"(c[2]),"+f"(c[3])
                 : "r"(a[0]),"r"(a[1]),"r"(a[2]),"r"(a[3]),"r"(b[0]),"r"(b[1]));
}
__device__ __forceinline__ void cp16(unsigned dst, const void* src) {
    asm volatile("cp.async.cg.shared.global [%0], [%1], 16;" :: "r"(dst), "l"(src));
}
__device__ __forceinline__ void cp_commit() { asm volatile("cp.async.commit_group;"); }
template<int N> __device__ __forceinline__ void cp_wait() {
    asm volatile("cp.async.wait_group %0;" :: "n"(N));
}

// ---------------------------------------------------------------------------
// One-shot weight converter: w_qkv_a, w_proj_a (fp32 [1024][64]) -> g_wah fp16.
// ---------------------------------------------------------------------------
__global__ __launch_bounds__(256) void convert_w_kernel(
    const float* __restrict__ wa, const float* __restrict__ wpa)
{
    int idx = blockIdx.x * 256 + threadIdx.x;      // 16384 threads x 4 elems
    float4 a = *(const float4*)&wa[idx * 4];
    float4 b = *(const float4*)&wpa[idx * 4];
    uint2 ua; ua.x = pack2(a.x, a.y); ua.y = pack2(a.z, a.w);
    uint2 ub; ub.x = pack2(b.x, b.y); ub.y = pack2(b.z, b.w);
    *(uint2*)&g_wah[idx * 4]               = ua;
    *(uint2*)&g_wah[KDIM*RANK + idx * 4]   = ub;
}

// ---------------------------------------------------------------------------
// out_fp16[M,64] = gelu(X[M,1024] @ W[1024,64] (+ bias)) via fp16 mma.
// X fp32 (XH=false) or fp16 (XH=true). 32-row tile, 64 threads (2 warps),
// K-chunks of 64, register prefetch double-buffer. Grid = M/32 = 128.
// ---------------------------------------------------------------------------
template<bool XH>
__global__ __launch_bounds__(64) void lowrank_a_mma_kernel(
    const float* __restrict__ Xf, const __half* __restrict__ Xh,
    const __half* __restrict__ Wh, const float* __restrict__ bias,
    __half* __restrict__ out)
{
    __shared__ __align__(16) __half Xs[32*72];
    __shared__ __align__(16) __half Ws[64*72];
    const int tid = threadIdx.x, lane = tid & 31, w = tid >> 5;
    const int m0 = blockIdx.x * 32;

    float4 xreg[8];   // fp32-X path
    uint4  xreg16[4]; // fp16-X path
    uint4  wreg[8];

    if (XH) {
        #pragma unroll
        for (int ii = 0; ii < 4; ii++) {
            int idx = tid + 64*ii, r = idx >> 3, c8 = (idx & 7) * 8;
            xreg16[ii] = *(const uint4*)&Xh[(m0 + r)*KDIM + c8];
        }
    } else {
        #pragma unroll
        for (int ii = 0; ii < 8; ii++) {
            int idx = tid + 64*ii, r = idx >> 4, c4 = (idx & 15) * 4;
            xreg[ii] = *(const float4*)&Xf[(m0 + r)*KDIM + c4];
        }
    }
    #pragma unroll
    for (int ii = 0; ii < 8; ii++) {
        int idx = tid + 64*ii, r = idx >> 3, c8 = (idx & 7) * 8;
        wreg[ii] = *(const uint4*)&Wh[r*RANK + c8];
    }

    const unsigned hA = (unsigned)__cvta_generic_to_shared(Xs)
                      + (unsigned)(((w*16 + (lane & 15))*72 + (lane >> 4)*8) * 2);
    const unsigned wB = (unsigned)__cvta_generic_to_shared(Ws)
                      + (unsigned)(((lane & 15)*72) * 2);

    float acc[8][4] = {};
    #pragma unroll 1
    for (int ch = 0; ch < KDIM/64; ch++) {
        if (XH) {
            #pragma unroll
            for (int ii = 0; ii < 4; ii++) {
                int idx = tid + 64*ii, r = idx >> 3, c8 = (idx & 7) * 8;
                *(uint4*)&Xs[r*72 + c8] = xreg16[ii];
            }
        } else {
            #pragma unroll
            for (int ii = 0; ii < 8; ii++) {
                int idx = tid + 64*ii, r = idx >> 4, c4 = (idx & 15) * 4;
                uint2 u; u.x = pack2(xreg[ii].x, xreg[ii].y);
                u.y = pack2(xreg[ii].z, xreg[ii].w);
                *(uint2*)&Xs[r*72 + c4] = u;
            }
        }
        #pragma unroll
        for (int ii = 0; ii < 8; ii++) {
            int idx = tid + 64*ii, r = idx >> 3, c8 = (idx & 7) * 8;
            *(uint4*)&Ws[r*72 + c8] = wreg[ii];
        }
        __syncthreads();
        if (ch + 1 < KDIM/64) {
            const int k0 = (ch + 1) * 64;
            if (XH) {
                #pragma unroll
                for (int ii = 0; ii < 4; ii++) {
                    int idx = tid + 64*ii, r = idx >> 3, c8 = (idx & 7) * 8;
                    xreg16[ii] = *(const uint4*)&Xh[(m0 + r)*KDIM + k0 + c8];
                }
            } else {
                #pragma unroll
                for (int ii = 0; ii < 8; ii++) {
                    int idx = tid + 64*ii, r = idx >> 4, c4 = (idx & 15) * 4;
                    xreg[ii] = *(const float4*)&Xf[(m0 + r)*KDIM + k0 + c4];
                }
            }
            #pragma unroll
            for (int ii = 0; ii < 8; ii++) {
                int idx = tid + 64*ii, r = idx >> 3, c8 = (idx & 7) * 8;
                wreg[ii] = *(const uint4*)&Wh[(k0 + r)*RANK + c8];
            }
        }
        #pragma unroll
        for (int ks = 0; ks < 4; ks++) {
            const int kk = ks * 16;
            unsigned af[4];
            ldsm4(af[0], af[1], af[2], af[3], hA + (unsigned)(kk * 2));
            #pragma unroll
            for (int j = 0; j < 8; j++) {
                unsigned bf[2];
                ldsm2t(bf[0], bf[1], wB + (unsigned)((kk*72 + j*8) * 2));
                mma16(acc[j], af, bf);
            }
        }
        __syncthreads();
    }

    const int rA = w*16 + (lane >> 2);
    #pragma unroll
    for (int j = 0; j < 8; j++) {
        int n = j*8 + (lane & 3)*2;
        float b0 = 0.f, b1 = 0.f;
        if (bias) { float2 bv = *(const float2*)&bias[n]; b0 = bv.x; b1 = bv.y; }
        *(unsigned*)&out[(m0 + rA    )*RANK + n] =
            pack2(gelu_exact(acc[j][0] + b0), gelu_exact(acc[j][1] + b1));
        *(unsigned*)&out[(m0 + rA + 8)*RANK + n] =
            pack2(gelu_exact(acc[j][2] + b0), gelu_exact(acc[j][3] + b1));
    }
}

// ---------------------------------------------------------------------------
// qkv = g_hh[4096,64] @ w_qkv_b[64,3072] via fp16 mma ->
//   g_qh (x 0.125*log2e), g_kh, g_vTh (transposed via SMEM staging).
// ---------------------------------------------------------------------------
__global__ __launch_bounds__(128) void expand_mma_kernel(const float* __restrict__ Wb)
{
    __shared__ __align__(16) __half Hs[64*72];      // A: rows m, cols k
    __shared__ __align__(16) __half Wsm[64*136];    // B: rows k, cols n (128+8 pad)
    const int tid = threadIdx.x, lane = tid & 31, w = tid >> 5;
    const int n0 = blockIdx.x * 128;
    const int m0 = blockIdx.y * 64;

    #pragma unroll
    for (int ii = 0; ii < 4; ii++) {
        int idx = tid + 128*ii, r = idx >> 3, c8 = (idx & 7) * 8;
        *(uint4*)&Hs[r*72 + c8] = *(const uint4*)&g_hh[(m0 + r)*64 + c8];
    }
    #pragma unroll
    for (int ii = 0; ii < 16; ii++) {
        int idx = tid + 128*ii, r = idx >> 5, c4 = (idx & 31) * 4;
        float4 v = *(const float4*)&Wb[r*(3*CDIM) + n0 + c4];
        uint2 u; u.x = pack2(v.x, v.y); u.y = pack2(v.z, v.w);
        *(uint2*)&Wsm[r*136 + c4] = u;
    }
    __syncthreads();

    const unsigned hA = (unsigned)__cvta_generic_to_shared(Hs)
                      + (unsigned)(((w*16 + (lane & 15))*72 + (lane >> 4)*8) * 2);
    const unsigned wB = (unsigned)__cvta_generic_to_shared(Wsm)
                      + (unsigned)(((lane & 15)*136) * 2);

    float acc[16][4] = {};
    #pragma unroll
    for (int ks = 0; ks < 4; ks++) {
        const int kk = ks * 16;
        unsigned af[4];
        ldsm4(af[0], af[1], af[2], af[3], hA + (unsigned)(kk * 2));
        #pragma unroll
        for (int j = 0; j < 16; j++) {
            unsigned bf[2];
            ldsm2t(bf[0], bf[1], wB + (unsigned)((kk*136 + j*8) * 2));
            mma16(acc[j], af, bf);
        }
    }

    const int comp = n0 >> 10;     // 0=q 1=k 2=v (uniform per block)
    const int bb   = m0 >> 11;
    const int ns0  = m0 & 2047;
    const int rA   = w*16 + (lane >> 2);

    if (comp < 2) {
        const float sc = (comp == 0) ? (0.125f * 1.44269504088896341f) : 1.0f;
        __half* dst = (comp == 0) ? g_qh : g_kh;
        #pragma unroll
        for (int j = 0; j < 16; j++) {
            int gn   = (n0 + j*8 + (lane & 3)*2) & 1023;
            int head = gn >> 6, d = gn & 63;
            size_t base = ((size_t)(bb*HEADS + head)*NSEQ + ns0);
            *(unsigned*)&dst[(base + rA    )*DH + d] = pack2(acc[j][0]*sc, acc[j][1]*sc);
            *(unsigned*)&dst[(base + rA + 8)*DH + d] = pack2(acc[j][2]*sc, acc[j][3]*sc);
        }
    } else {
        __syncthreads();                      // all ldsm reads done; reuse SMEM
        __half* Ts = Hs;                      // [128 c][72] halves
        #pragma unroll
        for (int j = 0; j < 16; j++) {
            int c = j*8 + (lane & 3)*2;
            Ts[(c+0)*72 + rA    ] = __float2half(acc[j][0]);
            Ts[(c+1)*72 + rA    ] = __float2half(acc[j][1]);
            Ts[(c+0)*72 + rA + 8] = __float2half(acc[j][2]);
            Ts[(c+1)*72 + rA + 8] = __float2half(acc[j][3]);
        }
        __syncthreads();
        int c    = tid;
        int gn   = (n0 + c) & 1023;
        int head = gn >> 6, d = gn & 63;
        size_t base = ((size_t)(bb*HEADS + head)*DH + d)*NSEQ + ns0;
        #pragma unroll
        for (int g = 0; g < 8; g++)
            *(uint4*)&g_vTh[base + g*8] = *(uint4*)&Ts[c*72 + g*8];
    }
}

// ---------------------------------------------------------------------------
// y[4096,1024] = g_h2h[4096,64] @ w_proj_b[64,1024] + b_proj_b   (fp16 mma)
// ---------------------------------------------------------------------------
__global__ __launch_bounds__(128) void lowrank_out_mma_kernel(
    const float* __restrict__ Wb, const float* __restrict__ bias,
    float* __restrict__ out)
{
    __shared__ __align__(16) __half Hs[64*72];
    __shared__ __align__(16) __half Wsm[64*136];
    const int tid = threadIdx.x, lane = tid & 31, w = tid >> 5;
    const int n0 = blockIdx.x * 128;
    const int m0 = blockIdx.y * 64;

    #pragma unroll
    for (int ii = 0; ii < 4; ii++) {
        int idx = tid + 128*ii, r = idx >> 3, c8 = (idx & 7) * 8;
        *(uint4*)&Hs[r*72 + c8] = *(const uint4*)&g_h2h[(m0 + r)*64 + c8];
    }
    #pragma unroll
    for (int ii = 0; ii < 16; ii++) {
        int idx = tid + 128*ii, r = idx >> 5, c4 = (idx & 31) * 4;
        float4 v = *(const float4*)&Wb[r*CDIM + n0 + c4];
        uint2 u; u.x = pack2(v.x, v.y); u.y = pack2(v.z, v.w);
        *(uint2*)&Wsm[r*136 + c4] = u;
    }
    __syncthreads();

    const unsigned hA = (unsigned)__cvta_generic_to_shared(Hs)
                      + (unsigned)(((w*16 + (lane & 15))*72 + (lane >> 4)*8) * 2);
    const unsigned wB = (unsigned)__cvta_generic_to_shared(Wsm)
                      + (unsigned)(((lane & 15)*136) * 2);

    float acc[16][4] = {};
    #pragma unroll
    for (int ks = 0; ks < 4; ks++) {
        const int kk = ks * 16;
        unsigned af[4];
        ldsm4(af[0], af[1], af[2], af[3], hA + (unsigned)(kk * 2));
        #pragma unroll
        for (int j = 0; j < 16; j++) {
            unsigned bf[2];
            ldsm2t(bf[0], bf[1], wB + (unsigned)((kk*136 + j*8) * 2));
            mma16(acc[j], af, bf);
        }
    }

    const int rA = w*16 + (lane >> 2);
    #pragma unroll
    for (int j = 0; j < 16; j++) {
        int n = n0 + j*8 + (lane & 3)*2;
        float2 bv = *(const float2*)&bias[n];
        size_t b0 = (size_t)(m0 + rA    )*CDIM + n;
        size_t b1 = (size_t)(m0 + rA + 8)*CDIM + n;
        *(float2*)&out[b0] = make_float2(acc[j][0] + bv.x, acc[j][1] + bv.y);
        *(float2*)&out[b1] = make_float2(acc[j][2] + bv.x, acc[j][3] + bv.y);
    }
}

// ---------------------------------------------------------------------------
// Flash attention, fp16 mma.m16n8k16, fp32 accum, exp2-domain softmax.
// Grid (NSEQ/128, B*H), 128 threads (4 warps). KV tile 64, 2-stage cp.async.
// P in registers. Output written fp16 to g_attnh [B,N,C].
// ---------------------------------------------------------------------------
#define LDH 72
#define FLASH_SMEM ((128 + 4*64) * LDH * 2)

__global__ __launch_bounds__(128) void flash_mma_kernel()
{
    extern __shared__ __align__(16) __half smh[];
    __half* Qs = smh;                                 // [128][LDH]

    const int tid  = threadIdx.x;
    const int lane = tid & 31, w = tid >> 5;
    const int bh = blockIdx.y;
    const int q0 = blockIdx.x * 128;
    const int b = bh >> 4, h = bh & 15;

    const __half* Qg  = g_qh  + ((size_t)bh * NSEQ + q0) * DH;
    const __half* Kg  = g_kh  + (size_t)bh * NSEQ * DH;
    const __half* VTg = g_vTh + (size_t)bh * DH * NSEQ;

    const unsigned sbase = (unsigned)__cvta_generic_to_shared(smh);

    {
        unsigned kdst = sbase + (unsigned)(128*LDH*2);
        unsigned vdst = kdst + (unsigned)(64*LDH*2);
        #pragma unroll
        for (int it = 0; it < 4; it++) {
            int i = tid + 128*it, r = i >> 3, c8 = (i & 7)*8;
            cp16(kdst + (unsigned)((r*LDH + c8)*2), &Kg[r*DH + c8]);
            cp16(vdst + (unsigned)((r*LDH + c8)*2), &VTg[(size_t)r*NSEQ + c8]);
        }
        cp_commit();
    }
    #pragma unroll
    for (int it = 0; it < 8; it++) {
        int i = tid + 128 * it, r = i >> 3, c8 = (i & 7) * 8;
        *(uint4*)&Qs[r*LDH + c8] = *(const uint4*)&Qg[r*DH + c8];
    }

    const unsigned aOff = (unsigned)((((lane & 15) * LDH) + (lane >> 4) * 8) * 2);
    const unsigned bOff = (unsigned)((((lane & 7) * LDH) + ((lane >> 3) & 1) * 8) * 2);
    const unsigned qsA = sbase + aOff;

    float o[2][8][4];
    float mrow[2][2], lrow[2][2];
    #pragma unroll
    for (int mt = 0; mt < 2; mt++) {
        mrow[mt][0] = mrow[mt][1] = -1e30f;
        lrow[mt][0] = lrow[mt][1] = 0.f;
        #pragma unroll
        for (int j = 0; j < 8; j++)
            o[mt][j][0] = o[mt][j][1] = o[mt][j][2] = o[mt][j][3] = 0.f;
    }

    for (int t = 0; t < NSEQ/64; t++) {
        if (t + 1 < NSEQ/64) {
            const __half* Kt = Kg + (size_t)(t+1) * 64 * DH;
            unsigned kdst = sbase + (unsigned)((128 + ((t+1)&1)*128)*LDH*2);
            unsigned vdst = kdst + (unsigned)(64*LDH*2);
            #pragma unroll
            for (int it = 0; it < 4; it++) {
                int i = tid + 128*it, r = i >> 3, c8 = (i & 7)*8;
                cp16(kdst + (unsigned)((r*LDH + c8)*2), &Kt[r*DH + c8]);
                cp16(vdst + (unsigned)((r*LDH + c8)*2), &VTg[(size_t)r*NSEQ + (t+1)*64 + c8]);
            }
            cp_commit();
            cp_wait<1>();
        } else {
            cp_wait<0>();
        }
        __syncthreads();

        const unsigned kB = sbase + (unsigned)((128 + (t&1)*128)*LDH*2) + bOff;
        const unsigned vB = kB + (unsigned)(64*LDH*2);

        // ---- S = Q K^T ----
        float s[2][8][4];
        #pragma unroll
        for (int mt = 0; mt < 2; mt++)
            #pragma unroll
            for (int j = 0; j < 8; j++)
                s[mt][j][0] = s[mt][j][1] = s[mt][j][2] = s[mt][j][3] = 0.f;

        #pragma unroll
        for (int ks = 0; ks < 4; ks++) {
            const int kk = ks * 16;
            unsigned bf[8][2];
            #pragma unroll
            for (int j = 0; j < 8; j++)
                ldsm2(bf[j][0], bf[j][1], kB + (unsigned)((j*8*LDH + kk) * 2));
            #pragma unroll
            for (int mt = 0; mt < 2; mt++) {
                unsigned af[4];
                ldsm4(af[0], af[1], af[2], af[3],
                      qsA + (unsigned)(((w*32 + mt*16)*LDH + kk) * 2));
                #pragma unroll
                for (int j = 0; j < 8; j++) mma16(s[mt][j], af, bf[j]);
            }
        }

        // ---- online softmax (log2 domain), P packed into registers ----
        unsigned pp[2][8][2];
        #pragma unroll
        for (int mt = 0; mt < 2; mt++) {
            float mxl = -1e30f, mxh = -1e30f;
            #pragma unroll
            for (int j = 0; j < 8; j++) {
                mxl = fmaxf(mxl, fmaxf(s[mt][j][0], s[mt][j][1]));
                mxh = fmaxf(mxh, fmaxf(s[mt][j][2], s[mt][j][3]));
            }
            mxl = fmaxf(mxl, __shfl_xor_sync(0xffffffffu, mxl, 1));
            mxl = fmaxf(mxl, __shfl_xor_sync(0xffffffffu, mxl, 2));
            mxh = fmaxf(mxh, __shfl_xor_sync(0xffffffffu, mxh, 1));
            mxh = fmaxf(mxh, __shfl_xor_sync(0xffffffffu, mxh, 2));
            float mln = fmaxf(mrow[mt][0], mxl);
            float mhn = fmaxf(mrow[mt][1], mxh);
            float al = exp2f(mrow[mt][0] - mln);
            float ah = exp2f(mrow[mt][1] - mhn);
            mrow[mt][0] = mln; mrow[mt][1] = mhn;
            float sl = 0.f, sh = 0.f;
            #pragma unroll
            for (int j = 0; j < 8; j++) {
                __half2 hl = __floats2half2_rn(exp2f(s[mt][j][0] - mln),
                                               exp2f(s[mt][j][1] - mln));
                __half2 hh = __floats2half2_rn(exp2f(s[mt][j][2] - mhn),
                                               exp2f(s[mt][j][3] - mhn));
                float2 fl = __half22float2(hl), fh = __half22float2(hh);
                sl += fl.x + fl.y; sh += fh.x + fh.y;
                pp[mt][j][0] = *(unsigned*)&hl;
                pp[mt][j][1] = *(unsigned*)&hh;
            }
            sl += __shfl_xor_sync(0xffffffffu, sl, 1);
            sl += __shfl_xor_sync(0xffffffffu, sl, 2);
            sh += __shfl_xor_sync(0xffffffffu, sh, 1);
            sh += __shfl_xor_sync(0xffffffffu, sh, 2);
            lrow[mt][0] = lrow[mt][0]*al + sl;
            lrow[mt][1] = lrow[mt][1]*ah + sh;
            #pragma unroll
            for (int j = 0; j < 8; j++) {
                o[mt][j][0] *= al; o[mt][j][1] *= al;
                o[mt][j][2] *= ah; o[mt][j][3] *= ah;
            }
        }

        // ---- O += P V ----
        #pragma unroll
        for (int ks = 0; ks < 4; ks++) {
            const int kc = ks * 16;
            unsigned bf[8][2];
            #pragma unroll
            for (int jd = 0; jd < 8; jd++)
                ldsm2(bf[jd][0], bf[jd][1], vB + (unsigned)((jd*8*LDH + kc) * 2));
            #pragma unroll
            for (int mt = 0; mt < 2; mt++) {
                unsigned af[4] = { pp[mt][2*ks][0], pp[mt][2*ks][1],
                                   pp[mt][2*ks+1][0], pp[mt][2*ks+1][1] };
                #pragma unroll
                for (int jd = 0; jd < 8; jd++) mma16(o[mt][jd], af, bf[jd]);
            }
        }
        __syncthreads();
    }

    // ---- epilogue: fp16 out to g_attnh [B,N,C] ----
    #pragma unroll
    for (int mt = 0; mt < 2; mt++) {
        float il = 1.0f / lrow[mt][0], ih = 1.0f / lrow[mt][1];
        int rowl = q0 + w*32 + mt*16 + (lane >> 2);
        size_t basel = ((size_t)(b*NSEQ + rowl))*CDIM + h*DH + (lane & 3)*2;
        size_t baseh = basel + (size_t)8*CDIM;
        #pragma unroll
        for (int j = 0; j < 8; j++) {
            *(unsigned*)&g_attnh[basel + j*8] = pack2(o[mt][j][0]*il, o[mt][j][1]*il);
            *(unsigned*)&g_attnh[baseh + j*8] = pack2(o[mt][j][2]*ih, o[mt][j][3]*ih);
        }
    }
}

// ---------------------------------------------------------------------------
extern "C" void kernel_launch(void* const* d_in, const int* in_sizes, int n_in,
                              void* d_out, int out_size)
{
    const float* x        = (const float*)d_in[0];
    const float* w_qkv_a  = (const float*)d_in[1];
    const float* w_qkv_b  = (const float*)d_in[2];
    const float* w_proj_a = (const float*)d_in[3];
    const float* b_proj_a = (const float*)d_in[4];
    const float* w_proj_b = (const float*)d_in[5];
    const float* b_proj_b = (const float*)d_in[6];
    float* out = (float*)d_out;

    __half *pwah = nullptr, *phh = nullptr, *ph2h = nullptr, *pattnh = nullptr;
    cudaGetSymbolAddress((void**)&pwah,   g_wah);
    cudaGetSymbolAddress((void**)&phh,    g_hh);
    cudaGetSymbolAddress((void**)&ph2h,   g_h2h);
    cudaGetSymbolAddress((void**)&pattnh, g_attnh);

    static bool attr_set = false;
    if (!attr_set) {
        cudaFuncSetAttribute(flash_mma_kernel,
                             cudaFuncAttributeMaxDynamicSharedMemorySize, FLASH_SMEM);
        attr_set = true;
    }

    // 0. fp16 weight staging for the two K=1024 "A" GEMMs
    convert_w_kernel<<<64, 256>>>(w_qkv_a, w_proj_a);
    // 1. h = gelu(x @ w_qkv_a)                 fp16 [4096,64]
    lowrank_a_mma_kernel<false><<<MTOT/32, 64>>>(x, nullptr, pwah, nullptr, phh);
    // 2. qkv = h @ w_qkv_b (mma) -> q (x0.125*log2e), k, vT  (fp16)
    expand_mma_kernel<<<dim3(3*CDIM/128, MTOT/64), 128>>>(w_qkv_b);
    // 3. fp16 tensor-core flash attention -> g_attnh [B,N,C] fp16
    flash_mma_kernel<<<dim3(NSEQ/128, BD*HEADS), 128, FLASH_SMEM>>>();
    // 4. h2 = gelu(attn @ w_proj_a + b_proj_a) fp16 [4096,64]
    lowrank_a_mma_kernel<true><<<MTOT/32, 64>>>(nullptr, pattnh, pwah + KDIM*RANK,
                                                b_proj_a, ph2h);
    // 5. y = h2 @ w_proj_b + b_proj_b (mma)    fp32 [4096,1024]
    lowrank_out_mma_kernel<<<dim3(CDIM/128, MTOT/64), 128>>>(w_proj_b, b_proj_b, out);
}